// round 12
// baseline (speedup 1.0000x reference)
#include <cuda_runtime.h>
#include <mma.h>
#include <cstdint>

using namespace nvcuda;

#define NIMG   4096
#define TSTEPS 128
#define BATCH  32
#define HID    128

// Scratch (device globals; no allocation allowed)
__device__ float g_z1[(size_t)NIMG * 4 * 400 * 8];    // conv1 out [n][c=ic/8][pix400][ic%8]
__device__ float g_z2[(size_t)NIMG * 4 * 81 * 16];    // conv2 out [n][cc=oc/16][pix81][oc%16]
__device__ float g_z3[(size_t)NIMG * 3136];           // conv3 out, NCHW flatten
__device__ float g_hidden[(size_t)NIMG * 512];        // FC out
__device__ float g_gates[(size_t)NIMG * 512];         // x-proj of gates (+both biases)
__device__ float g_hs[(size_t)NIMG * HID];            // per-step hidden outputs
__device__ float g_whhT[HID * 512];                   // W_hh transposed
__device__ float g_w1t[64 * 32];                      // W1/255 in [k][oc] (tf32-rounded)
__device__ float g_w2t[512 * 64];                     // W2 in [k][oc]  (tf32-rounded)
__device__ float g_w3t[576 * 64];                     // W3 in [k][oc]  (tf32-rounded)

// ---------------------------------------------------------------------------
// Weight re-layout preps
// ---------------------------------------------------------------------------
__global__ __launch_bounds__(256) void w1t_kernel(const float* __restrict__ W1) {
    const int id = blockIdx.x * 256 + threadIdx.x;
    const int k = id >> 5, oc = id & 31;
    g_w1t[k * 32 + oc] = wmma::__float_to_tf32(W1[oc * 64 + k] * (1.0f / 255.0f));
}
__global__ __launch_bounds__(256) void w2t_kernel(const float* __restrict__ W2) {
    const int id = blockIdx.x * 256 + threadIdx.x;
    const int k = id >> 6, oc = id & 63;
    const int c = k >> 7, k16 = (k & 127) >> 3, icl = k & 7;
    g_w2t[k * 64 + oc] = wmma::__float_to_tf32(W2[oc * 512 + (c * 8 + icl) * 16 + k16]);
}
__global__ __launch_bounds__(256) void w3t_kernel(const float* __restrict__ W3) {
    const int id = blockIdx.x * 256 + threadIdx.x;
    const int k = id >> 6, oc = id & 63;
    const int icc = k / 144, rem = k % 144, k9 = rem >> 4, icl = rem & 15;
    g_w3t[k * 64 + oc] = wmma::__float_to_tf32(W3[oc * 576 + (icc * 16 + icl) * 9 + k9]);
}
__global__ __launch_bounds__(512) void whh_transpose_kernel(const float* __restrict__ W_hh) {
    const int id = blockIdx.x * 512 + threadIdx.x;
    const int k = id >> 9, j = id & 511;
    g_whhT[k * 512 + j] = W_hh[j * 128 + k];
}

// ---------------------------------------------------------------------------
// conv1 TF32 WMMA (r11 proven): M=1638400, N=32, K=64, 128-row tile.
// ---------------------------------------------------------------------------
#define LDA 136
#define LDB 72
#define LDC 72
#define LDB1 36
#define LDC1 36

typedef wmma::fragment<wmma::accumulator, 16, 16, 8, float> AccFrag;
typedef wmma::fragment<wmma::matrix_a, 16, 16, 8, wmma::precision::tf32, wmma::col_major> AFrag;
typedef wmma::fragment<wmma::matrix_b, 16, 16, 8, wmma::precision::tf32, wmma::row_major> BFrag;

#define STAGE_A8L(dst, ld, ar, kb, v0, v1)                            \
    {                                                                 \
        (dst)[((kb) + 0) * (ld) + (ar)] = wmma::__float_to_tf32(v0.x);\
        (dst)[((kb) + 1) * (ld) + (ar)] = wmma::__float_to_tf32(v0.y);\
        (dst)[((kb) + 2) * (ld) + (ar)] = wmma::__float_to_tf32(v0.z);\
        (dst)[((kb) + 3) * (ld) + (ar)] = wmma::__float_to_tf32(v0.w);\
        (dst)[((kb) + 4) * (ld) + (ar)] = wmma::__float_to_tf32(v1.x);\
        (dst)[((kb) + 5) * (ld) + (ar)] = wmma::__float_to_tf32(v1.y);\
        (dst)[((kb) + 6) * (ld) + (ar)] = wmma::__float_to_tf32(v1.z);\
        (dst)[((kb) + 7) * (ld) + (ar)] = wmma::__float_to_tf32(v1.w);\
    }

__global__ __launch_bounds__(256) void conv1_wmma_kernel(const float* __restrict__ x,
                                                         const float* __restrict__ b1) {
    __shared__ float smem[5504];
    const int tid = threadIdx.x;
    const int wid = tid >> 5, wm = wid >> 1, wn = wid & 1;
    const int m0 = blockIdx.x * 128;
    const int ar = tid >> 1, q = tid & 1;
    const int m = m0 + ar;
    const int an = m / 400, ap = m % 400;
    const int iy = (ap / 20) * 4, ix = (ap % 20) * 4;
    const float* xrow = x + (size_t)an * 7056 + ix;
    const int kb = tid >> 3, ob = (tid & 7) << 2;

    AccFrag acc1[2];
#pragma unroll
    for (int i = 0; i < 2; i++) wmma::fill_fragment(acc1[i], 0.f);

    float* As = smem;
    float* Bs = smem + 4352;

#define C1_LOADA(k0, v0, v1)                                   \
    {                                                          \
        const int ky = ((k0) >> 3) + q;                        \
        const float* xp = xrow + (iy + ky) * 84;               \
        v0 = *(const float4*)(xp);                             \
        v1 = *(const float4*)(xp + 4);                         \
    }

    {
        float4 a0, a1;
        C1_LOADA(0, a0, a1);
        float4 bv;
        if (tid < 128) bv = *(const float4*)&g_w1t[kb * 32 + ob];
        STAGE_A8L(As, LDA, ar, q * 8, a0, a1);
        if (tid < 128) *(float4*)&Bs[kb * LDB1 + ob] = bv;
    }
    __syncthreads();

    int buf = 0;
    for (int k0 = 16; k0 < 64; k0 += 16) {
        float4 a0, a1;
        C1_LOADA(k0, a0, a1);
        float4 bv;
        if (tid < 128) bv = *(const float4*)&g_w1t[(k0 + kb) * 32 + ob];
#pragma unroll
        for (int ks = 0; ks < 16; ks += 8) {
            AFrag a[2]; BFrag b;
#pragma unroll
            for (int i = 0; i < 2; i++)
                wmma::load_matrix_sync(a[i], As + buf * 2176 + ks * LDA + wm * 32 + i * 16, LDA);
            wmma::load_matrix_sync(b, Bs + buf * 576 + ks * LDB1 + wn * 16, LDB1);
#pragma unroll
            for (int i = 0; i < 2; i++)
                wmma::mma_sync(acc1[i], a[i], b, acc1[i]);
        }
        float* An = As + (buf ^ 1) * 2176;
        float* Bn = Bs + (buf ^ 1) * 576;
        STAGE_A8L(An, LDA, ar, q * 8, a0, a1);
        if (tid < 128) *(float4*)&Bn[kb * LDB1 + ob] = bv;
        __syncthreads();
        buf ^= 1;
    }
#pragma unroll
    for (int ks = 0; ks < 16; ks += 8) {
        AFrag a[2]; BFrag b;
#pragma unroll
        for (int i = 0; i < 2; i++)
            wmma::load_matrix_sync(a[i], As + buf * 2176 + ks * LDA + wm * 32 + i * 16, LDA);
        wmma::load_matrix_sync(b, Bs + buf * 576 + ks * LDB1 + wn * 16, LDB1);
#pragma unroll
        for (int i = 0; i < 2; i++)
            wmma::mma_sync(acc1[i], a[i], b, acc1[i]);
    }
    __syncthreads();
#pragma unroll
    for (int i = 0; i < 2; i++)
        wmma::store_matrix_sync(&smem[(wm * 32 + i * 16) * LDC1 + wn * 16], acc1[i],
                                LDC1, wmma::mem_row_major);
    __syncthreads();

    const int r = tid >> 1, h = tid & 1;
    const int rn = (m0 + r) / 400, rp = (m0 + r) % 400;
#pragma unroll
    for (int j = 0; j < 2; j++) {
        const int oc4 = h * 16 + j * 8;
#pragma unroll
        for (int s = 0; s < 2; s++) {
            const int oc = oc4 + s * 4;
            float4 v = *(float4*)&smem[r * LDC1 + oc];
            const float4 bb = *(const float4*)&b1[oc];
            v.x = fmaxf(v.x + bb.x, 0.f);
            v.y = fmaxf(v.y + bb.y, 0.f);
            v.z = fmaxf(v.z + bb.z, 0.f);
            v.w = fmaxf(v.w + bb.w, 0.f);
            const int g = oc >> 3, l = oc & 7;
            *(float4*)&g_z1[((size_t)rn * 4 + g) * 3200 + rp * 8 + l] = v;
        }
    }
}

// ---------------------------------------------------------------------------
// M=256 x N=64 TF32 tile machinery: 8 warps, warp grid 4x2, warp tile 64x32.
// smem floats: As 2x4224 @0, Bs 2x1152 @8448. Epilogue C-stage reuses front.
// ---------------------------------------------------------------------------
#define LDA2 264

__device__ __forceinline__ void mma_chunk256(const float* __restrict__ As,
                                             const float* __restrict__ Bs,
                                             AccFrag (&acc)[4][2], int wm, int wn) {
#pragma unroll
    for (int ks = 0; ks < 16; ks += 8) {
        AFrag a[4]; BFrag b[2];
#pragma unroll
        for (int i = 0; i < 4; i++)
            wmma::load_matrix_sync(a[i], As + ks * LDA2 + wm * 64 + i * 16, LDA2);
#pragma unroll
        for (int j = 0; j < 2; j++)
            wmma::load_matrix_sync(b[j], Bs + ks * LDB + wn * 32 + j * 16, LDB);
#pragma unroll
        for (int i = 0; i < 4; i++)
#pragma unroll
            for (int j = 0; j < 2; j++)
                wmma::mma_sync(acc[i][j], a[i], b[j], acc[i][j]);
    }
}

// ---------------------------------------------------------------------------
// conv2 TF32 M=256: M=331776, K=512, N=64.
// ---------------------------------------------------------------------------
__global__ __launch_bounds__(256) void conv2_wmma_kernel(const float* __restrict__ b2) {
    __shared__ float smem[10752];
    const int tid = threadIdx.x;
    const int wid = tid >> 5, wm = wid >> 1, wn = wid & 1;
    const int m0 = blockIdx.x * 256;
    const int ar = tid;
    const int m = m0 + ar;
    const int an = m / 81, ap = m % 81;
    const int aiy = (ap / 9) * 2, aix = (ap % 9) * 2;
    const int kb = tid >> 4, ob = (tid & 15) << 2;

    AccFrag acc[4][2];
#pragma unroll
    for (int i = 0; i < 4; i++)
#pragma unroll
        for (int j = 0; j < 2; j++) wmma::fill_fragment(acc[i][j], 0.f);

#define AS2(buf) (smem + (buf) * 4224)
#define BS2(buf) (smem + 8448 + (buf) * 1152)

#define C2_LOAD_STAGE(dst, k0)                                                    \
    {                                                                             \
        _Pragma("unroll")                                                         \
        for (int qq = 0; qq < 2; qq++) {                                          \
            const int g = ((k0) >> 3) + qq;                                       \
            const int c = g >> 4, k16 = g & 15;                                   \
            const int ky = k16 >> 2, kx = k16 & 3;                                \
            const float* p = &g_z1[(((size_t)an * 4 + c) * 400 +                  \
                                    (aiy + ky) * 20 + aix + kx) * 8];             \
            const float4 v0 = *(const float4*)p;                                  \
            const float4 v1 = *(const float4*)(p + 4);                            \
            STAGE_A8L(dst, LDA2, ar, qq * 8, v0, v1);                             \
        }                                                                         \
    }

    {
        C2_LOAD_STAGE(AS2(0), 0);
        *(float4*)&BS2(0)[kb * LDB + ob] = *(const float4*)&g_w2t[(size_t)kb * 64 + ob];
    }
    __syncthreads();

    int buf = 0;
    for (int k0 = 16; k0 < 512; k0 += 16) {
        const float4 bv = *(const float4*)&g_w2t[(size_t)(k0 + kb) * 64 + ob];
        mma_chunk256(AS2(buf), BS2(buf), acc, wm, wn);
        C2_LOAD_STAGE(AS2(buf ^ 1), k0);
        *(float4*)&BS2(buf ^ 1)[kb * LDB + ob] = bv;
        __syncthreads();
        buf ^= 1;
    }
    mma_chunk256(AS2(buf), BS2(buf), acc, wm, wn);
    __syncthreads();

    const float4 bbx = *(const float4*)&b2[(tid & 1) * 32 + 0];  // dummy warm
    (void)bbx;
#pragma unroll
    for (int w = 0; w < 2; w++) {
        if ((wm >> 1) == w) {
#pragma unroll
            for (int i = 0; i < 4; i++)
#pragma unroll
                for (int j = 0; j < 2; j++)
                    wmma::store_matrix_sync(
                        &smem[((wm & 1) * 64 + i * 16) * LDC + wn * 32 + j * 16],
                        acc[i][j], LDC, wmma::mem_row_major);
        }
        __syncthreads();
        const int r = tid >> 1, h = tid & 1;
        const int mm = m0 + w * 128 + r;
        const int rn = mm / 81, rp = mm % 81;
#pragma unroll
        for (int j = 0; j < 8; j++) {
            const int oc = h * 32 + j * 4;
            float4 v = *(float4*)&smem[r * LDC + oc];
            const float4 bb = *(const float4*)&b2[oc];
            v.x = fmaxf(v.x + bb.x, 0.f);
            v.y = fmaxf(v.y + bb.y, 0.f);
            v.z = fmaxf(v.z + bb.z, 0.f);
            v.w = fmaxf(v.w + bb.w, 0.f);
            *(float4*)&g_z2[(((size_t)rn * 4 + (oc >> 4)) * 81 + rp) * 16 + (oc & 15)] = v;
        }
        __syncthreads();
    }
}

// ---------------------------------------------------------------------------
// conv3 TF32 M=256: M=200704, K=576, N=64. 16 consecutive k = one address.
// ---------------------------------------------------------------------------
__global__ __launch_bounds__(256) void conv3_wmma_kernel(const float* __restrict__ b3) {
    __shared__ float smem[10752];
    const int tid = threadIdx.x;
    const int wid = tid >> 5, wm = wid >> 1, wn = wid & 1;
    const int m0 = blockIdx.x * 256;
    const int ar = tid;
    const int m = m0 + ar;
    const int an = m / 49, ap = m % 49;
    const int aoy = ap / 7, aox = ap % 7;
    const int kb = tid >> 4, ob = (tid & 15) << 2;

    AccFrag acc[4][2];
#pragma unroll
    for (int i = 0; i < 4; i++)
#pragma unroll
        for (int j = 0; j < 2; j++) wmma::fill_fragment(acc[i][j], 0.f);

#define C3_LOAD_STAGE(dst, k0)                                                    \
    {                                                                             \
        const int g = (k0) >> 4;                                                  \
        const int icc = g / 9, k9 = g % 9;                                        \
        const int ky = k9 / 3, kx = k9 % 3;                                       \
        const float* p = &g_z2[(((size_t)an * 4 + icc) * 81 +                     \
                                (aoy + ky) * 9 + aox + kx) * 16];                 \
        const float4 u0 = *(const float4*)p;                                      \
        const float4 u1 = *(const float4*)(p + 4);                                \
        const float4 u2 = *(const float4*)(p + 8);                                \
        const float4 u3 = *(const float4*)(p + 12);                               \
        STAGE_A8L(dst, LDA2, ar, 0, u0, u1);                                      \
        STAGE_A8L(dst, LDA2, ar, 8, u2, u3);                                      \
    }

    {
        C3_LOAD_STAGE(AS2(0), 0);
        *(float4*)&BS2(0)[kb * LDB + ob] = *(const float4*)&g_w3t[(size_t)kb * 64 + ob];
    }
    __syncthreads();

    int buf = 0;
    for (int k0 = 16; k0 < 576; k0 += 16) {
        const float4 bv = *(const float4*)&g_w3t[(size_t)(k0 + kb) * 64 + ob];
        mma_chunk256(AS2(buf), BS2(buf), acc, wm, wn);
        C3_LOAD_STAGE(AS2(buf ^ 1), k0);
        *(float4*)&BS2(buf ^ 1)[kb * LDB + ob] = bv;
        __syncthreads();
        buf ^= 1;
    }
    mma_chunk256(AS2(buf), BS2(buf), acc, wm, wn);
    __syncthreads();

#pragma unroll
    for (int w = 0; w < 2; w++) {
        if ((wm >> 1) == w) {
#pragma unroll
            for (int i = 0; i < 4; i++)
#pragma unroll
                for (int j = 0; j < 2; j++)
                    wmma::store_matrix_sync(
                        &smem[((wm & 1) * 64 + i * 16) * LDC + wn * 32 + j * 16],
                        acc[i][j], LDC, wmma::mem_row_major);
        }
        __syncthreads();
        const int r = tid >> 1, h = tid & 1;
        const int mm = m0 + w * 128 + r;
        const int rn = mm / 49, rp = mm % 49;
#pragma unroll
        for (int j = 0; j < 8; j++) {
            const int oc = h * 32 + j * 4;
            const float4 v = *(float4*)&smem[r * LDC + oc];
            const float4 bb = *(const float4*)&b3[oc];
            float* zp = &g_z3[(size_t)rn * 3136 + oc * 49 + rp];
            zp[0]   = fmaxf(v.x + bb.x, 0.f);
            zp[49]  = fmaxf(v.y + bb.y, 0.f);
            zp[98]  = fmaxf(v.z + bb.z, 0.f);
            zp[147] = fmaxf(v.w + bb.w, 0.f);
        }
        __syncthreads();
    }
}

// ---------------------------------------------------------------------------
// Dense TF32 GEMM M=256 (fc / gates): C = A[M,K] B[N,K]^T + biases.
// ---------------------------------------------------------------------------
__device__ __forceinline__ void gemm_wmma256(const float* __restrict__ A,
                                             const float* __restrict__ B,
                                             float* __restrict__ C, int K,
                                             const float* __restrict__ bias1,
                                             const float* __restrict__ bias2,
                                             bool relu) {
    __shared__ float smem[10752];
    const int tid = threadIdx.x;
    const int wid = tid >> 5, wm = wid >> 1, wn = wid & 1;
    const int m0 = blockIdx.y * 256, n0 = blockIdx.x * 64;
    const int ar = tid;
    const int bn = tid >> 2, bq = tid & 3;
    const float* Ap = A + (size_t)(m0 + ar) * K;
    const float* Bp = B + (size_t)(n0 + bn) * K + bq * 4;

    AccFrag acc[4][2];
#pragma unroll
    for (int i = 0; i < 4; i++)
#pragma unroll
        for (int j = 0; j < 2; j++) wmma::fill_fragment(acc[i][j], 0.f);

#define G_LOAD_STAGE(dst, k0)                                                     \
    {                                                                             \
        const float4 u0 = *(const float4*)(Ap + (k0));                            \
        const float4 u1 = *(const float4*)(Ap + (k0) + 4);                        \
        const float4 u2 = *(const float4*)(Ap + (k0) + 8);                        \
        const float4 u3 = *(const float4*)(Ap + (k0) + 12);                       \
        STAGE_A8L(dst, LDA2, ar, 0, u0, u1);                                      \
        STAGE_A8L(dst, LDA2, ar, 8, u2, u3);                                      \
    }

#define G_STAGE_B(dst, bv)                                                  \
    (dst)[(bq * 4 + 0) * LDB + bn] = wmma::__float_to_tf32(bv.x);           \
    (dst)[(bq * 4 + 1) * LDB + bn] = wmma::__float_to_tf32(bv.y);           \
    (dst)[(bq * 4 + 2) * LDB + bn] = wmma::__float_to_tf32(bv.z);           \
    (dst)[(bq * 4 + 3) * LDB + bn] = wmma::__float_to_tf32(bv.w);

    {
        G_LOAD_STAGE(AS2(0), 0);
        const float4 bv = *(const float4*)(Bp);
        G_STAGE_B(BS2(0), bv);
    }
    __syncthreads();

    int buf = 0;
    for (int k0 = 16; k0 < K; k0 += 16) {
        const float4 bv = *(const float4*)(Bp + k0);
        mma_chunk256(AS2(buf), BS2(buf), acc, wm, wn);
        G_LOAD_STAGE(AS2(buf ^ 1), k0);
        G_STAGE_B(BS2(buf ^ 1), bv);
        __syncthreads();
        buf ^= 1;
    }
    mma_chunk256(AS2(buf), BS2(buf), acc, wm, wn);
    __syncthreads();

#pragma unroll
    for (int w = 0; w < 2; w++) {
        if ((wm >> 1) == w) {
#pragma unroll
            for (int i = 0; i < 4; i++)
#pragma unroll
                for (int j = 0; j < 2; j++)
                    wmma::store_matrix_sync(
                        &smem[((wm & 1) * 64 + i * 16) * LDC + wn * 32 + j * 16],
                        acc[i][j], LDC, wmma::mem_row_major);
        }
        __syncthreads();
        const int r = tid >> 1, h = tid & 1;
        const int mm = m0 + w * 128 + r;
#pragma unroll
        for (int j = 0; j < 8; j++) {
            const int c = h * 32 + j * 4;
            float4 v = *(float4*)&smem[r * LDC + c];
            const float b0 = bias1[n0 + c + 0] + (bias2 ? bias2[n0 + c + 0] : 0.f);
            const float b1v = bias1[n0 + c + 1] + (bias2 ? bias2[n0 + c + 1] : 0.f);
            const float b2v = bias1[n0 + c + 2] + (bias2 ? bias2[n0 + c + 2] : 0.f);
            const float b3v = bias1[n0 + c + 3] + (bias2 ? bias2[n0 + c + 3] : 0.f);
            v.x += b0; v.y += b1v; v.z += b2v; v.w += b3v;
            if (relu) {
                v.x = fmaxf(v.x, 0.f); v.y = fmaxf(v.y, 0.f);
                v.z = fmaxf(v.z, 0.f); v.w = fmaxf(v.w, 0.f);
            }
            *(float4*)&C[(size_t)mm * 512 + n0 + c] = v;
        }
        __syncthreads();
    }
}

__global__ __launch_bounds__(256) void fc_gemm_kernel(const float* __restrict__ Wfc,
                                                      const float* __restrict__ bfc) {
    gemm_wmma256(g_z3, Wfc, g_hidden, 3136, bfc, nullptr, true);
}
__global__ __launch_bounds__(256) void gates_gemm_kernel(const float* __restrict__ W_ih,
                                                         const float* __restrict__ b_ih,
                                                         const float* __restrict__ b_hh) {
    gemm_wmma256(g_hidden, W_ih, g_gates, 512, b_ih, b_hh, false);
}

// ---------------------------------------------------------------------------
// LSTM: one block per batch element, 512 threads (proven coalesced, fp32).
// ---------------------------------------------------------------------------
__device__ __forceinline__ float sigmoidf_(float v) {
    return 1.0f / (1.0f + __expf(-v));
}

__global__ __launch_bounds__(512) void lstm_kernel(const float* __restrict__ done,
                                                   const float* __restrict__ h0,
                                                   const float* __restrict__ c0,
                                                   float* __restrict__ out) {
    __shared__ float hm[HID];
    __shared__ float cs[HID];
    __shared__ float hs[HID];
    __shared__ float part[4 * 512];
    const int b = blockIdx.x;
    const int tid = threadIdx.x;
    const int j4 = tid & 127;
    const int ks = tid >> 7;

    if (tid < HID) {
        hs[tid] = h0[b * HID + tid];
        cs[tid] = c0[b * HID + tid];
    }
    __syncthreads();

    for (int t = 0; t < TSTEPS; t++) {
        const float mask = 1.0f - done[t * BATCH + b];
        if (tid < HID) hm[tid] = hs[tid] * mask;
        __syncthreads();

        float a0 = 0.f, a1 = 0.f, a2 = 0.f, a3 = 0.f;
        const float4* __restrict__ wt = (const float4*)&g_whhT[(ks * 32) * 512] + j4;
        const float* __restrict__ hk = &hm[ks * 32];
#pragma unroll
        for (int kk = 0; kk < 32; kk++) {
            const float4 w = wt[kk * 128];
            const float h = hk[kk];
            a0 += w.x * h; a1 += w.y * h; a2 += w.z * h; a3 += w.w * h;
        }
        float4 pv = {a0, a1, a2, a3};
        *(float4*)&part[ks * 512 + j4 * 4] = pv;
        __syncthreads();

        const float gx = g_gates[(size_t)(t * BATCH + b) * 512 + tid];
        const float gsum = part[tid] + part[512 + tid] + part[1024 + tid] +
                           part[1536 + tid] + gx;
        part[tid] = gsum;
        __syncthreads();

        if (tid < HID) {
            const float gi = part[tid];
            const float gf = part[tid + 128];
            const float gc = part[tid + 256];
            const float go = part[tid + 384];
            float c = cs[tid] * mask;
            c = sigmoidf_(gf) * c + sigmoidf_(gi) * tanhf(gc);
            const float h = sigmoidf_(go) * tanhf(c);
            cs[tid] = c;
            hs[tid] = h;
            g_hs[(size_t)(t * BATCH + b) * HID + tid] = h;
            if (t == TSTEPS - 1) {
                out[28672 + b * HID + tid] = h;
                out[32768 + b * HID + tid] = c;
            }
        }
        __syncthreads();
    }
}

// ---------------------------------------------------------------------------
// Heads: logits (4096x6) and value (4096x1) from g_hs.
// ---------------------------------------------------------------------------
__global__ __launch_bounds__(256) void heads_kernel(const float* __restrict__ Wa,
                                                    const float* __restrict__ ba,
                                                    const float* __restrict__ Wc,
                                                    const float* __restrict__ bc,
                                                    float* __restrict__ out) {
    __shared__ float was[6 * 128];
    __shared__ float wcs[128];
    __shared__ float bas[6];
    __shared__ float bcs;
    const int tid = threadIdx.x;
    for (int i = tid; i < 768; i += 256) was[i] = Wa[i];
    if (tid < 128) wcs[tid] = Wc[tid];
    if (tid < 6) bas[tid] = ba[tid];
    if (tid == 0) bcs = bc[0];
    __syncthreads();

    const int row = blockIdx.x * 256 + tid;
    const float* hp = &g_hs[(size_t)row * 128];
    float acc[6] = {0.f, 0.f, 0.f, 0.f, 0.f, 0.f};
    float accv = 0.f;
    for (int k = 0; k < 128; k += 4) {
        const float4 h4 = *(const float4*)&hp[k];
#pragma unroll
        for (int a = 0; a < 6; a++) {
            const float4 w4 = *(const float4*)&was[a * 128 + k];
            acc[a] += h4.x * w4.x + h4.y * w4.y + h4.z * w4.z + h4.w * w4.w;
        }
        const float4 wc4 = *(const float4*)&wcs[k];
        accv += h4.x * wc4.x + h4.y * wc4.y + h4.z * wc4.z + h4.w * wc4.w;
    }
#pragma unroll
    for (int a = 0; a < 6; a++) out[row * 6 + a] = acc[a] + bas[a];
    out[24576 + row] = accv + bcs;
}

// ---------------------------------------------------------------------------
// Launch
// ---------------------------------------------------------------------------
extern "C" void kernel_launch(void* const* d_in, const int* in_sizes, int n_in,
                              void* d_out, int out_size) {
    const float* x    = (const float*)d_in[0];
    const float* done = (const float*)d_in[1];
    const float* h0   = (const float*)d_in[2];
    const float* c0   = (const float*)d_in[3];
    const float* W1   = (const float*)d_in[4];
    const float* b1   = (const float*)d_in[5];
    const float* W2   = (const float*)d_in[6];
    const float* b2   = (const float*)d_in[7];
    const float* W3   = (const float*)d_in[8];
    const float* b3   = (const float*)d_in[9];
    const float* Wfc  = (const float*)d_in[10];
    const float* bfc  = (const float*)d_in[11];
    const float* W_ih = (const float*)d_in[12];
    const float* W_hh = (const float*)d_in[13];
    const float* b_ih = (const float*)d_in[14];
    const float* b_hh = (const float*)d_in[15];
    const float* Wa   = (const float*)d_in[16];
    const float* ba   = (const float*)d_in[17];
    const float* Wc   = (const float*)d_in[18];
    const float* bc   = (const float*)d_in[19];
    float* out = (float*)d_out;

    whh_transpose_kernel<<<128, 512>>>(W_hh);
    w1t_kernel<<<8, 256>>>(W1);
    w2t_kernel<<<128, 256>>>(W2);
    w3t_kernel<<<144, 256>>>(W3);
    conv1_wmma_kernel<<<12800, 256>>>(x, b1);
    conv2_wmma_kernel<<<1296, 256>>>(b2);
    conv3_wmma_kernel<<<784, 256>>>(b3);
    fc_gemm_kernel<<<dim3(8, 16), 256>>>(Wfc, bfc);
    gates_gemm_kernel<<<dim3(8, 16), 256>>>(W_ih, b_ih, b_hh);
    lstm_kernel<<<BATCH, 512>>>(done, h0, c0, out);
    heads_kernel<<<16, 256>>>(Wa, ba, Wc, bc, out);
}

// round 13
// speedup vs baseline: 1.1070x; 1.1070x over previous
#include <cuda_runtime.h>
#include <mma.h>
#include <cstdint>

using namespace nvcuda;

#define NIMG   4096
#define TSTEPS 128
#define BATCH  32
#define HID    128

// Scratch (device globals; no allocation allowed)
__device__ float g_z1[(size_t)NIMG * 4 * 400 * 8];    // conv1 out [n][c=ic/8][pix400][ic%8]
__device__ float g_z2[(size_t)NIMG * 4 * 81 * 16];    // conv2 out [n][cc=oc/16][pix81][oc%16]
__device__ float g_z3[(size_t)NIMG * 3136];           // conv3 out, NCHW flatten
__device__ float g_hidden[(size_t)NIMG * 512];        // FC out
__device__ float g_gates[(size_t)NIMG * 512];         // x-proj of gates (+both biases)
__device__ float g_hs[(size_t)NIMG * HID];            // per-step hidden outputs
__device__ float g_whhT[HID * 512];                   // W_hh transposed
__device__ float g_w1t[64 * 32];                      // W1/255 in [k][oc] (tf32-rounded)
__device__ float g_w2t[512 * 64];                     // W2 in [k][oc]  (tf32-rounded)
__device__ float g_w3t[576 * 64];                     // W3 in [k][oc]  (tf32-rounded)

// ---------------------------------------------------------------------------
// Weight re-layout preps
// ---------------------------------------------------------------------------
__global__ __launch_bounds__(256) void w1t_kernel(const float* __restrict__ W1) {
    const int id = blockIdx.x * 256 + threadIdx.x;
    const int k = id >> 5, oc = id & 31;
    g_w1t[k * 32 + oc] = wmma::__float_to_tf32(W1[oc * 64 + k] * (1.0f / 255.0f));
}
__global__ __launch_bounds__(256) void w2t_kernel(const float* __restrict__ W2) {
    const int id = blockIdx.x * 256 + threadIdx.x;
    const int k = id >> 6, oc = id & 63;
    const int c = k >> 7, k16 = (k & 127) >> 3, icl = k & 7;
    g_w2t[k * 64 + oc] = wmma::__float_to_tf32(W2[oc * 512 + (c * 8 + icl) * 16 + k16]);
}
__global__ __launch_bounds__(256) void w3t_kernel(const float* __restrict__ W3) {
    const int id = blockIdx.x * 256 + threadIdx.x;
    const int k = id >> 6, oc = id & 63;
    const int icc = k / 144, rem = k % 144, k9 = rem >> 4, icl = rem & 15;
    g_w3t[k * 64 + oc] = wmma::__float_to_tf32(W3[oc * 576 + (icc * 16 + icl) * 9 + k9]);
}
__global__ __launch_bounds__(512) void whh_transpose_kernel(const float* __restrict__ W_hh) {
    const int id = blockIdx.x * 512 + threadIdx.x;
    const int k = id >> 9, j = id & 511;
    g_whhT[k * 512 + j] = W_hh[j * 128 + k];
}

// ---------------------------------------------------------------------------
// Common WMMA defs
// ---------------------------------------------------------------------------
#define LDA 136
#define LDB 72
#define LDC 72
#define LDB1 36
#define LDC1 36

typedef wmma::fragment<wmma::accumulator, 16, 16, 8, float> AccFrag;
typedef wmma::fragment<wmma::matrix_a, 16, 16, 8, wmma::precision::tf32, wmma::col_major> AFrag;
typedef wmma::fragment<wmma::matrix_b, 16, 16, 8, wmma::precision::tf32, wmma::row_major> BFrag;

#define STAGE_A8L(dst, ld, ar, kb, v0, v1)                            \
    {                                                                 \
        (dst)[((kb) + 0) * (ld) + (ar)] = wmma::__float_to_tf32(v0.x);\
        (dst)[((kb) + 1) * (ld) + (ar)] = wmma::__float_to_tf32(v0.y);\
        (dst)[((kb) + 2) * (ld) + (ar)] = wmma::__float_to_tf32(v0.z);\
        (dst)[((kb) + 3) * (ld) + (ar)] = wmma::__float_to_tf32(v0.w);\
        (dst)[((kb) + 4) * (ld) + (ar)] = wmma::__float_to_tf32(v1.x);\
        (dst)[((kb) + 5) * (ld) + (ar)] = wmma::__float_to_tf32(v1.y);\
        (dst)[((kb) + 6) * (ld) + (ar)] = wmma::__float_to_tf32(v1.z);\
        (dst)[((kb) + 7) * (ld) + (ar)] = wmma::__float_to_tf32(v1.w);\
    }

// 32-deep chunk: 4 slabs of 8 k
__device__ __forceinline__ void mma_chunk32(const float* __restrict__ As,
                                            const float* __restrict__ Bs,
                                            AccFrag (&acc)[2][2], int wm, int wn) {
#pragma unroll
    for (int ks = 0; ks < 32; ks += 8) {
        AFrag a[2]; BFrag b[2];
#pragma unroll
        for (int i = 0; i < 2; i++)
            wmma::load_matrix_sync(a[i], As + ks * LDA + wm * 32 + i * 16, LDA);
#pragma unroll
        for (int j = 0; j < 2; j++)
            wmma::load_matrix_sync(b[j], Bs + ks * LDB + wn * 32 + j * 16, LDB);
#pragma unroll
        for (int i = 0; i < 2; i++)
#pragma unroll
            for (int j = 0; j < 2; j++)
                wmma::mma_sync(acc[i][j], a[i], b[j], acc[i][j]);
    }
}

__device__ __forceinline__ void store_c_frags(float* smem, AccFrag (&acc)[2][2],
                                              int wm, int wn) {
#pragma unroll
    for (int i = 0; i < 2; i++)
#pragma unroll
        for (int j = 0; j < 2; j++)
            wmma::store_matrix_sync(&smem[(wm * 32 + i * 16) * LDC + wn * 32 + j * 16],
                                    acc[i][j], LDC, wmma::mem_row_major);
}

// dynamic smem layout for BK=32 kernels (floats):
// As: 2 x 32*136 = 8704 @0 ; Bs: 2 x 32*72 = 4608 @8704 ; total 13312 floats
#define AS32(sm, buf) ((sm) + (size_t)(buf) * 4352)
#define BS32(sm, buf) ((sm) + 8704 + (size_t)(buf) * 2304)
#define CW_SMEM_BYTES (13312 * 4)

// ---------------------------------------------------------------------------
// conv1 TF32 WMMA (r11 proven): M=1638400, N=32, K=64, 128-row tile, static smem.
// ---------------------------------------------------------------------------
__global__ __launch_bounds__(256) void conv1_wmma_kernel(const float* __restrict__ x,
                                                         const float* __restrict__ b1) {
    __shared__ float smem[5504];
    const int tid = threadIdx.x;
    const int wid = tid >> 5, wm = wid >> 1, wn = wid & 1;
    const int m0 = blockIdx.x * 128;
    const int ar = tid >> 1, q = tid & 1;
    const int m = m0 + ar;
    const int an = m / 400, ap = m % 400;
    const int iy = (ap / 20) * 4, ix = (ap % 20) * 4;
    const float* xrow = x + (size_t)an * 7056 + ix;
    const int kb = tid >> 3, ob = (tid & 7) << 2;

    AccFrag acc1[2];
#pragma unroll
    for (int i = 0; i < 2; i++) wmma::fill_fragment(acc1[i], 0.f);

    float* As = smem;
    float* Bs = smem + 4352;

#define C1_LOADA(k0, v0, v1)                                   \
    {                                                          \
        const int ky = ((k0) >> 3) + q;                        \
        const float* xp = xrow + (iy + ky) * 84;               \
        v0 = *(const float4*)(xp);                             \
        v1 = *(const float4*)(xp + 4);                         \
    }

    {
        float4 a0, a1;
        C1_LOADA(0, a0, a1);
        float4 bv;
        if (tid < 128) bv = *(const float4*)&g_w1t[kb * 32 + ob];
        STAGE_A8L(As, LDA, ar, q * 8, a0, a1);
        if (tid < 128) *(float4*)&Bs[kb * LDB1 + ob] = bv;
    }
    __syncthreads();

    int buf = 0;
    for (int k0 = 16; k0 < 64; k0 += 16) {
        float4 a0, a1;
        C1_LOADA(k0, a0, a1);
        float4 bv;
        if (tid < 128) bv = *(const float4*)&g_w1t[(k0 + kb) * 32 + ob];
#pragma unroll
        for (int ks = 0; ks < 16; ks += 8) {
            AFrag a[2]; BFrag b;
#pragma unroll
            for (int i = 0; i < 2; i++)
                wmma::load_matrix_sync(a[i], As + buf * 2176 + ks * LDA + wm * 32 + i * 16, LDA);
            wmma::load_matrix_sync(b, Bs + buf * 576 + ks * LDB1 + wn * 16, LDB1);
#pragma unroll
            for (int i = 0; i < 2; i++)
                wmma::mma_sync(acc1[i], a[i], b, acc1[i]);
        }
        float* An = As + (buf ^ 1) * 2176;
        float* Bn = Bs + (buf ^ 1) * 576;
        STAGE_A8L(An, LDA, ar, q * 8, a0, a1);
        if (tid < 128) *(float4*)&Bn[kb * LDB1 + ob] = bv;
        __syncthreads();
        buf ^= 1;
    }
#pragma unroll
    for (int ks = 0; ks < 16; ks += 8) {
        AFrag a[2]; BFrag b;
#pragma unroll
        for (int i = 0; i < 2; i++)
            wmma::load_matrix_sync(a[i], As + buf * 2176 + ks * LDA + wm * 32 + i * 16, LDA);
        wmma::load_matrix_sync(b, Bs + buf * 576 + ks * LDB1 + wn * 16, LDB1);
#pragma unroll
        for (int i = 0; i < 2; i++)
            wmma::mma_sync(acc1[i], a[i], b, acc1[i]);
    }
    __syncthreads();
#pragma unroll
    for (int i = 0; i < 2; i++)
        wmma::store_matrix_sync(&smem[(wm * 32 + i * 16) * LDC1 + wn * 16], acc1[i],
                                LDC1, wmma::mem_row_major);
    __syncthreads();

    const int r = tid >> 1, h = tid & 1;
    const int rn = (m0 + r) / 400, rp = (m0 + r) % 400;
#pragma unroll
    for (int j = 0; j < 2; j++) {
        const int oc4 = h * 16 + j * 8;
#pragma unroll
        for (int s = 0; s < 2; s++) {
            const int oc = oc4 + s * 4;
            float4 v = *(float4*)&smem[r * LDC1 + oc];
            const float4 bb = *(const float4*)&b1[oc];
            v.x = fmaxf(v.x + bb.x, 0.f);
            v.y = fmaxf(v.y + bb.y, 0.f);
            v.z = fmaxf(v.z + bb.z, 0.f);
            v.w = fmaxf(v.w + bb.w, 0.f);
            const int g = oc >> 3, l = oc & 7;
            *(float4*)&g_z1[((size_t)rn * 4 + g) * 3200 + rp * 8 + l] = v;
        }
    }
}

// ---------------------------------------------------------------------------
// conv2 TF32, BK=32: M=331776, K=512, N=64. Dynamic smem 53KB.
// ---------------------------------------------------------------------------
__global__ __launch_bounds__(256) void conv2_wmma_kernel(const float* __restrict__ b2) {
    extern __shared__ float sm2[];
    const int tid = threadIdx.x;
    const int wid = tid >> 5, wm = wid >> 1, wn = wid & 1;
    const int m0 = blockIdx.x * 128;
    const int ar = tid >> 1, q = tid & 1;
    const int m = m0 + ar;
    const int an = m / 81, ap = m % 81;
    const int aiy = (ap / 9) * 2, aix = (ap % 9) * 2;
    const int kb = tid >> 4, ob = (tid & 15) << 2;

    AccFrag acc[2][2];
#pragma unroll
    for (int i = 0; i < 2; i++)
#pragma unroll
        for (int j = 0; j < 2; j++) wmma::fill_fragment(acc[i][j], 0.f);

#define C2_STAGE32(dst, k0)                                                       \
    {                                                                             \
        _Pragma("unroll")                                                         \
        for (int half = 0; half < 2; half++) {                                    \
            const int g = ((k0) >> 3) + half * 2 + q;                             \
            const int c = g >> 4, k16 = g & 15;                                   \
            const int ky = k16 >> 2, kx = k16 & 3;                                \
            const float* p = &g_z1[(((size_t)an * 4 + c) * 400 +                  \
                                    (aiy + ky) * 20 + aix + kx) * 8];             \
            const float4 v0 = *(const float4*)p;                                  \
            const float4 v1 = *(const float4*)(p + 4);                            \
            STAGE_A8L(dst, LDA, ar, (half * 2 + q) * 8, v0, v1);                  \
        }                                                                         \
    }

#define STAGE_B32(dst, wsrc, k0)                                                  \
    {                                                                             \
        _Pragma("unroll")                                                         \
        for (int pass = 0; pass < 2; pass++) {                                    \
            const int row = kb + pass * 16;                                       \
            *(float4*)&(dst)[row * LDB + ob] =                                    \
                *(const float4*)&wsrc[(size_t)((k0) + row) * 64 + ob];            \
        }                                                                         \
    }

    {
        C2_STAGE32(AS32(sm2, 0), 0);
        STAGE_B32(BS32(sm2, 0), g_w2t, 0);
    }
    __syncthreads();

    int buf = 0;
    for (int k0 = 32; k0 < 512; k0 += 32) {
        mma_chunk32(AS32(sm2, buf), BS32(sm2, buf), acc, wm, wn);
        C2_STAGE32(AS32(sm2, buf ^ 1), k0);
        STAGE_B32(BS32(sm2, buf ^ 1), g_w2t, k0);
        __syncthreads();
        buf ^= 1;
    }
    mma_chunk32(AS32(sm2, buf), BS32(sm2, buf), acc, wm, wn);
    __syncthreads();
    store_c_frags(sm2, acc, wm, wn);
    __syncthreads();

    const int r = tid >> 1, h = tid & 1;
    const int rn = (m0 + r) / 81, rp = (m0 + r) % 81;
#pragma unroll
    for (int j = 0; j < 8; j++) {
        const int oc = h * 32 + j * 4;
        float4 v = *(float4*)&sm2[r * LDC + oc];
        const float4 bb = *(const float4*)&b2[oc];
        v.x = fmaxf(v.x + bb.x, 0.f);
        v.y = fmaxf(v.y + bb.y, 0.f);
        v.z = fmaxf(v.z + bb.z, 0.f);
        v.w = fmaxf(v.w + bb.w, 0.f);
        *(float4*)&g_z2[(((size_t)rn * 4 + (oc >> 4)) * 81 + rp) * 16 + (oc & 15)] = v;
    }
}

// ---------------------------------------------------------------------------
// conv3 TF32, BK=32: M=200704, K=576, N=64. Dynamic smem 53KB.
// ---------------------------------------------------------------------------
__global__ __launch_bounds__(256) void conv3_wmma_kernel(const float* __restrict__ b3) {
    extern __shared__ float sm3[];
    const int tid = threadIdx.x;
    const int wid = tid >> 5, wm = wid >> 1, wn = wid & 1;
    const int m0 = blockIdx.x * 128;
    const int ar = tid >> 1, q = tid & 1;
    const int m = m0 + ar;
    const int an = m / 49, ap = m % 49;
    const int aoy = ap / 7, aox = ap % 7;
    const int kb = tid >> 4, ob = (tid & 15) << 2;

    AccFrag acc[2][2];
#pragma unroll
    for (int i = 0; i < 2; i++)
#pragma unroll
        for (int j = 0; j < 2; j++) wmma::fill_fragment(acc[i][j], 0.f);

#define C3_STAGE32(dst, k0)                                                       \
    {                                                                             \
        _Pragma("unroll")                                                         \
        for (int half = 0; half < 2; half++) {                                    \
            const int g = ((k0) >> 4) + half;                                     \
            const int icc = g / 9, k9 = g % 9;                                    \
            const int ky = k9 / 3, kx = k9 % 3;                                   \
            const float* p = &g_z2[(((size_t)an * 4 + icc) * 81 +                 \
                                    (aoy + ky) * 9 + aox + kx) * 16 + q * 8];     \
            const float4 v0 = *(const float4*)p;                                  \
            const float4 v1 = *(const float4*)(p + 4);                            \
            STAGE_A8L(dst, LDA, ar, half * 16 + q * 8, v0, v1);                   \
        }                                                                         \
    }

    {
        C3_STAGE32(AS32(sm3, 0), 0);
        STAGE_B32(BS32(sm3, 0), g_w3t, 0);
    }
    __syncthreads();

    int buf = 0;
    for (int k0 = 32; k0 < 576; k0 += 32) {
        mma_chunk32(AS32(sm3, buf), BS32(sm3, buf), acc, wm, wn);
        C3_STAGE32(AS32(sm3, buf ^ 1), k0);
        STAGE_B32(BS32(sm3, buf ^ 1), g_w3t, k0);
        __syncthreads();
        buf ^= 1;
    }
    mma_chunk32(AS32(sm3, buf), BS32(sm3, buf), acc, wm, wn);
    __syncthreads();
    store_c_frags(sm3, acc, wm, wn);
    __syncthreads();

    const int r = tid >> 1, h = tid & 1;
    const int rn = (m0 + r) / 49, rp = (m0 + r) % 49;
#pragma unroll
    for (int j = 0; j < 8; j++) {
        const int oc = h * 32 + j * 4;
        const float4 v = *(float4*)&sm3[r * LDC + oc];
        const float4 bb = *(const float4*)&b3[oc];
        float* zp = &g_z3[(size_t)rn * 3136 + oc * 49 + rp];
        zp[0]   = fmaxf(v.x + bb.x, 0.f);
        zp[49]  = fmaxf(v.y + bb.y, 0.f);
        zp[98]  = fmaxf(v.z + bb.z, 0.f);
        zp[147] = fmaxf(v.w + bb.w, 0.f);
    }
}

// ---------------------------------------------------------------------------
// Dense TF32 GEMM BK=32 (fc / gates). Dynamic smem 53KB.
// ---------------------------------------------------------------------------
__device__ __forceinline__ void gemm_wmma32(const float* __restrict__ A,
                                            const float* __restrict__ B,
                                            float* __restrict__ C, int K,
                                            const float* __restrict__ bias1,
                                            const float* __restrict__ bias2,
                                            bool relu, float* sm) {
    const int tid = threadIdx.x;
    const int wid = tid >> 5, wm = wid >> 1, wn = wid & 1;
    const int m0 = blockIdx.y * 128, n0 = blockIdx.x * 64;
    const int ar = tid >> 1, q = tid & 1;
    const int bn = tid >> 2, bq = tid & 3;
    const float* Ap = A + (size_t)(m0 + ar) * K;
    const float* Bp = B + (size_t)(n0 + bn) * K;

    AccFrag acc[2][2];
#pragma unroll
    for (int i = 0; i < 2; i++)
#pragma unroll
        for (int j = 0; j < 2; j++) wmma::fill_fragment(acc[i][j], 0.f);

#define G_STAGE_A32(dst, k0)                                                      \
    {                                                                             \
        _Pragma("unroll")                                                         \
        for (int half = 0; half < 2; half++) {                                    \
            const int kk = (k0) + half * 16 + q * 8;                              \
            const float4 u0 = *(const float4*)(Ap + kk);                          \
            const float4 u1 = *(const float4*)(Ap + kk + 4);                      \
            STAGE_A8L(dst, LDA, ar, half * 16 + q * 8, u0, u1);                   \
        }                                                                         \
    }

#define G_STAGE_B32(dst, k0)                                                      \
    {                                                                             \
        _Pragma("unroll")                                                         \
        for (int half = 0; half < 2; half++) {                                    \
            const int kk = (k0) + half * 16 + bq * 4;                             \
            const float4 bv = *(const float4*)(Bp + kk);                          \
            const int rb = half * 16 + bq * 4;                                    \
            (dst)[(rb + 0) * LDB + bn] = wmma::__float_to_tf32(bv.x);             \
            (dst)[(rb + 1) * LDB + bn] = wmma::__float_to_tf32(bv.y);             \
            (dst)[(rb + 2) * LDB + bn] = wmma::__float_to_tf32(bv.z);             \
            (dst)[(rb + 3) * LDB + bn] = wmma::__float_to_tf32(bv.w);             \
        }                                                                         \
    }

    {
        G_STAGE_A32(AS32(sm, 0), 0);
        G_STAGE_B32(BS32(sm, 0), 0);
    }
    __syncthreads();

    int buf = 0;
    for (int k0 = 32; k0 < K; k0 += 32) {
        mma_chunk32(AS32(sm, buf), BS32(sm, buf), acc, wm, wn);
        G_STAGE_A32(AS32(sm, buf ^ 1), k0);
        G_STAGE_B32(BS32(sm, buf ^ 1), k0);
        __syncthreads();
        buf ^= 1;
    }
    mma_chunk32(AS32(sm, buf), BS32(sm, buf), acc, wm, wn);
    __syncthreads();
    store_c_frags(sm, acc, wm, wn);
    __syncthreads();

    const int r = tid >> 1, h = tid & 1;
#pragma unroll
    for (int j = 0; j < 8; j++) {
        const int c = h * 32 + j * 4;
        float4 v = *(float4*)&sm[r * LDC + c];
        const float b0 = bias1[n0 + c + 0] + (bias2 ? bias2[n0 + c + 0] : 0.f);
        const float b1v = bias1[n0 + c + 1] + (bias2 ? bias2[n0 + c + 1] : 0.f);
        const float b2v = bias1[n0 + c + 2] + (bias2 ? bias2[n0 + c + 2] : 0.f);
        const float b3v = bias1[n0 + c + 3] + (bias2 ? bias2[n0 + c + 3] : 0.f);
        v.x += b0; v.y += b1v; v.z += b2v; v.w += b3v;
        if (relu) {
            v.x = fmaxf(v.x, 0.f); v.y = fmaxf(v.y, 0.f);
            v.z = fmaxf(v.z, 0.f); v.w = fmaxf(v.w, 0.f);
        }
        *(float4*)&C[(size_t)(m0 + r) * 512 + n0 + c] = v;
    }
}

__global__ __launch_bounds__(256) void fc_gemm_kernel(const float* __restrict__ Wfc,
                                                      const float* __restrict__ bfc) {
    extern __shared__ float smf[];
    gemm_wmma32(g_z3, Wfc, g_hidden, 3136, bfc, nullptr, true, smf);
}
__global__ __launch_bounds__(256) void gates_gemm_kernel(const float* __restrict__ W_ih,
                                                         const float* __restrict__ b_ih,
                                                         const float* __restrict__ b_hh) {
    extern __shared__ float smg[];
    gemm_wmma32(g_hidden, W_ih, g_gates, 512, b_ih, b_hh, false, smg);
}

// ---------------------------------------------------------------------------
// LSTM: one block per batch element, 512 threads (proven coalesced, fp32).
// ---------------------------------------------------------------------------
__device__ __forceinline__ float sigmoidf_(float v) {
    return 1.0f / (1.0f + __expf(-v));
}

__global__ __launch_bounds__(512) void lstm_kernel(const float* __restrict__ done,
                                                   const float* __restrict__ h0,
                                                   const float* __restrict__ c0,
                                                   float* __restrict__ out) {
    __shared__ float hm[HID];
    __shared__ float cs[HID];
    __shared__ float hs[HID];
    __shared__ float part[4 * 512];
    const int b = blockIdx.x;
    const int tid = threadIdx.x;
    const int j4 = tid & 127;
    const int ks = tid >> 7;

    if (tid < HID) {
        hs[tid] = h0[b * HID + tid];
        cs[tid] = c0[b * HID + tid];
    }
    __syncthreads();

    for (int t = 0; t < TSTEPS; t++) {
        const float mask = 1.0f - done[t * BATCH + b];
        if (tid < HID) hm[tid] = hs[tid] * mask;
        __syncthreads();

        float a0 = 0.f, a1 = 0.f, a2 = 0.f, a3 = 0.f;
        const float4* __restrict__ wt = (const float4*)&g_whhT[(ks * 32) * 512] + j4;
        const float* __restrict__ hk = &hm[ks * 32];
#pragma unroll
        for (int kk = 0; kk < 32; kk++) {
            const float4 w = wt[kk * 128];
            const float h = hk[kk];
            a0 += w.x * h; a1 += w.y * h; a2 += w.z * h; a3 += w.w * h;
        }
        float4 pv = {a0, a1, a2, a3};
        *(float4*)&part[ks * 512 + j4 * 4] = pv;
        __syncthreads();

        const float gx = g_gates[(size_t)(t * BATCH + b) * 512 + tid];
        const float gsum = part[tid] + part[512 + tid] + part[1024 + tid] +
                           part[1536 + tid] + gx;
        part[tid] = gsum;
        __syncthreads();

        if (tid < HID) {
            const float gi = part[tid];
            const float gf = part[tid + 128];
            const float gc = part[tid + 256];
            const float go = part[tid + 384];
            float c = cs[tid] * mask;
            c = sigmoidf_(gf) * c + sigmoidf_(gi) * tanhf(gc);
            const float h = sigmoidf_(go) * tanhf(c);
            cs[tid] = c;
            hs[tid] = h;
            g_hs[(size_t)(t * BATCH + b) * HID + tid] = h;
            if (t == TSTEPS - 1) {
                out[28672 + b * HID + tid] = h;
                out[32768 + b * HID + tid] = c;
            }
        }
        __syncthreads();
    }
}

// ---------------------------------------------------------------------------
// Heads: logits (4096x6) and value (4096x1) from g_hs.
// ---------------------------------------------------------------------------
__global__ __launch_bounds__(256) void heads_kernel(const float* __restrict__ Wa,
                                                    const float* __restrict__ ba,
                                                    const float* __restrict__ Wc,
                                                    const float* __restrict__ bc,
                                                    float* __restrict__ out) {
    __shared__ float was[6 * 128];
    __shared__ float wcs[128];
    __shared__ float bas[6];
    __shared__ float bcs;
    const int tid = threadIdx.x;
    for (int i = tid; i < 768; i += 256) was[i] = Wa[i];
    if (tid < 128) wcs[tid] = Wc[tid];
    if (tid < 6) bas[tid] = ba[tid];
    if (tid == 0) bcs = bc[0];
    __syncthreads();

    const int row = blockIdx.x * 256 + tid;
    const float* hp = &g_hs[(size_t)row * 128];
    float acc[6] = {0.f, 0.f, 0.f, 0.f, 0.f, 0.f};
    float accv = 0.f;
    for (int k = 0; k < 128; k += 4) {
        const float4 h4 = *(const float4*)&hp[k];
#pragma unroll
        for (int a = 0; a < 6; a++) {
            const float4 w4 = *(const float4*)&was[a * 128 + k];
            acc[a] += h4.x * w4.x + h4.y * w4.y + h4.z * w4.z + h4.w * w4.w;
        }
        const float4 wc4 = *(const float4*)&wcs[k];
        accv += h4.x * wc4.x + h4.y * wc4.y + h4.z * wc4.z + h4.w * wc4.w;
    }
#pragma unroll
    for (int a = 0; a < 6; a++) out[row * 6 + a] = acc[a] + bas[a];
    out[24576 + row] = accv + bcs;
}

// ---------------------------------------------------------------------------
// Launch
// ---------------------------------------------------------------------------
extern "C" void kernel_launch(void* const* d_in, const int* in_sizes, int n_in,
                              void* d_out, int out_size) {
    const float* x    = (const float*)d_in[0];
    const float* done = (const float*)d_in[1];
    const float* h0   = (const float*)d_in[2];
    const float* c0   = (const float*)d_in[3];
    const float* W1   = (const float*)d_in[4];
    const float* b1   = (const float*)d_in[5];
    const float* W2   = (const float*)d_in[6];
    const float* b2   = (const float*)d_in[7];
    const float* W3   = (const float*)d_in[8];
    const float* b3   = (const float*)d_in[9];
    const float* Wfc  = (const float*)d_in[10];
    const float* bfc  = (const float*)d_in[11];
    const float* W_ih = (const float*)d_in[12];
    const float* W_hh = (const float*)d_in[13];
    const float* b_ih = (const float*)d_in[14];
    const float* b_hh = (const float*)d_in[15];
    const float* Wa   = (const float*)d_in[16];
    const float* ba   = (const float*)d_in[17];
    const float* Wc   = (const float*)d_in[18];
    const float* bc   = (const float*)d_in[19];
    float* out = (float*)d_out;

    static bool attr_done = false;
    if (!attr_done) {
        cudaFuncSetAttribute(conv2_wmma_kernel,
                             cudaFuncAttributeMaxDynamicSharedMemorySize, CW_SMEM_BYTES);
        cudaFuncSetAttribute(conv3_wmma_kernel,
                             cudaFuncAttributeMaxDynamicSharedMemorySize, CW_SMEM_BYTES);
        cudaFuncSetAttribute(fc_gemm_kernel,
                             cudaFuncAttributeMaxDynamicSharedMemorySize, CW_SMEM_BYTES);
        cudaFuncSetAttribute(gates_gemm_kernel,
                             cudaFuncAttributeMaxDynamicSharedMemorySize, CW_SMEM_BYTES);
        attr_done = true;
    }

    whh_transpose_kernel<<<128, 512>>>(W_hh);
    w1t_kernel<<<8, 256>>>(W1);
    w2t_kernel<<<128, 256>>>(W2);
    w3t_kernel<<<144, 256>>>(W3);
    conv1_wmma_kernel<<<12800, 256>>>(x, b1);
    conv2_wmma_kernel<<<2592, 256, CW_SMEM_BYTES>>>(b2);
    conv3_wmma_kernel<<<1568, 256, CW_SMEM_BYTES>>>(b3);
    fc_gemm_kernel<<<dim3(8, 32), 256, CW_SMEM_BYTES>>>(Wfc, bfc);
    gates_gemm_kernel<<<dim3(8, 32), 256, CW_SMEM_BYTES>>>(W_ih, b_ih, b_hh);
    lstm_kernel<<<BATCH, 512>>>(done, h0, c0, out);
    heads_kernel<<<16, 256>>>(Wa, ba, Wc, bc, out);
}

// round 14
// speedup vs baseline: 1.1191x; 1.0109x over previous
#include <cuda_runtime.h>
#include <mma.h>
#include <cstdint>

using namespace nvcuda;

#define NIMG   4096
#define TSTEPS 128
#define BATCH  32
#define HID    128

// Scratch (device globals; no allocation allowed)
__device__ float g_z1[(size_t)NIMG * 4 * 400 * 8];    // conv1 out (tf32-rounded)
__device__ float g_z2[(size_t)NIMG * 4 * 81 * 16];    // conv2 out (tf32-rounded)
__device__ float g_z3[(size_t)NIMG * 3136];           // conv3 out (tf32-rounded)
__device__ float g_hidden[(size_t)NIMG * 512];        // FC out (tf32-rounded)
__device__ float g_gates[(size_t)NIMG * 512];         // x-proj of gates (fp32)
__device__ float g_hs[(size_t)NIMG * HID];            // per-step hidden outputs
__device__ float g_whhT[HID * 512];                   // W_hh transposed
__device__ float g_w1t[64 * 32];                      // W1/255 [k][oc] (tf32)
__device__ float g_w2t[512 * 64];                     // W2 [k][oc] (tf32)
__device__ float g_w3t[576 * 64];                     // W3 [k][oc] (tf32)
__device__ float g_wfcT[3136 * 512];                  // Wfc [k][n] (tf32)
__device__ float g_wihT[512 * 512];                   // W_ih [k][n] (tf32)

// ---------------------------------------------------------------------------
// Weight re-layout preps (all tf32-rounded)
// ---------------------------------------------------------------------------
__global__ __launch_bounds__(256) void w1t_kernel(const float* __restrict__ W1) {
    const int id = blockIdx.x * 256 + threadIdx.x;
    const int k = id >> 5, oc = id & 31;
    g_w1t[k * 32 + oc] = wmma::__float_to_tf32(W1[oc * 64 + k] * (1.0f / 255.0f));
}
__global__ __launch_bounds__(256) void w2t_kernel(const float* __restrict__ W2) {
    const int id = blockIdx.x * 256 + threadIdx.x;
    const int k = id >> 6, oc = id & 63;
    const int c = k >> 7, k16 = (k & 127) >> 3, icl = k & 7;
    g_w2t[k * 64 + oc] = wmma::__float_to_tf32(W2[oc * 512 + (c * 8 + icl) * 16 + k16]);
}
__global__ __launch_bounds__(256) void w3t_kernel(const float* __restrict__ W3) {
    const int id = blockIdx.x * 256 + threadIdx.x;
    const int k = id >> 6, oc = id & 63;
    const int icc = k / 144, rem = k % 144, k9 = rem >> 4, icl = rem & 15;
    g_w3t[k * 64 + oc] = wmma::__float_to_tf32(W3[oc * 576 + (icc * 16 + icl) * 9 + k9]);
}
__global__ __launch_bounds__(256) void wfct_kernel(const float* __restrict__ Wfc) {
    const int id = blockIdx.x * 256 + threadIdx.x;   // 0..1605631
    const int k = id >> 9, n = id & 511;
    g_wfcT[(size_t)k * 512 + n] = wmma::__float_to_tf32(Wfc[(size_t)n * 3136 + k]);
}
__global__ __launch_bounds__(256) void wiht_kernel(const float* __restrict__ W_ih) {
    const int id = blockIdx.x * 256 + threadIdx.x;   // 0..262143
    const int k = id >> 9, n = id & 511;
    g_wihT[k * 512 + n] = wmma::__float_to_tf32(W_ih[n * 512 + k]);
}
__global__ __launch_bounds__(512) void whh_transpose_kernel(const float* __restrict__ W_hh) {
    const int id = blockIdx.x * 512 + threadIdx.x;
    const int k = id >> 9, j = id & 511;
    g_whhT[k * 512 + j] = W_hh[j * 128 + k];
}

// ---------------------------------------------------------------------------
// Common WMMA defs
// ---------------------------------------------------------------------------
#define LDA 136
#define LDB 72
#define LDC 72
#define LDB1 36
#define LDC1 36

typedef wmma::fragment<wmma::accumulator, 16, 16, 8, float> AccFrag;
typedef wmma::fragment<wmma::matrix_a, 16, 16, 8, wmma::precision::tf32, wmma::col_major> AFrag;
typedef wmma::fragment<wmma::matrix_b, 16, 16, 8, wmma::precision::tf32, wmma::row_major> BFrag;

// raw copy (values already tf32-valid)
#define STAGE_A8(dst, ar, kb, v0, v1)        \
    {                                        \
        (dst)[((kb) + 0) * LDA + (ar)] = v0.x; \
        (dst)[((kb) + 1) * LDA + (ar)] = v0.y; \
        (dst)[((kb) + 2) * LDA + (ar)] = v0.z; \
        (dst)[((kb) + 3) * LDA + (ar)] = v0.w; \
        (dst)[((kb) + 4) * LDA + (ar)] = v1.x; \
        (dst)[((kb) + 5) * LDA + (ar)] = v1.y; \
        (dst)[((kb) + 6) * LDA + (ar)] = v1.z; \
        (dst)[((kb) + 7) * LDA + (ar)] = v1.w; \
    }

// converting copy (external input, conv1 only)
#define STAGE_A8C(dst, ar, kb, v0, v1)                                \
    {                                                                 \
        (dst)[((kb) + 0) * LDA + (ar)] = wmma::__float_to_tf32(v0.x); \
        (dst)[((kb) + 1) * LDA + (ar)] = wmma::__float_to_tf32(v0.y); \
        (dst)[((kb) + 2) * LDA + (ar)] = wmma::__float_to_tf32(v0.z); \
        (dst)[((kb) + 3) * LDA + (ar)] = wmma::__float_to_tf32(v0.w); \
        (dst)[((kb) + 4) * LDA + (ar)] = wmma::__float_to_tf32(v1.x); \
        (dst)[((kb) + 5) * LDA + (ar)] = wmma::__float_to_tf32(v1.y); \
        (dst)[((kb) + 6) * LDA + (ar)] = wmma::__float_to_tf32(v1.z); \
        (dst)[((kb) + 7) * LDA + (ar)] = wmma::__float_to_tf32(v1.w); \
    }

__device__ __forceinline__ void mma_chunk(const float* __restrict__ As,
                                          const float* __restrict__ Bs,
                                          AccFrag (&acc)[2][2], int wm, int wn) {
#pragma unroll
    for (int ks = 0; ks < 16; ks += 8) {
        AFrag a[2]; BFrag b[2];
#pragma unroll
        for (int i = 0; i < 2; i++)
            wmma::load_matrix_sync(a[i], As + ks * LDA + wm * 32 + i * 16, LDA);
#pragma unroll
        for (int j = 0; j < 2; j++)
            wmma::load_matrix_sync(b[j], Bs + ks * LDB + wn * 32 + j * 16, LDB);
#pragma unroll
        for (int i = 0; i < 2; i++)
#pragma unroll
            for (int j = 0; j < 2; j++)
                wmma::mma_sync(acc[i][j], a[i], b[j], acc[i][j]);
    }
}

__device__ __forceinline__ void store_c_frags(float* smem, AccFrag (&acc)[2][2],
                                              int wm, int wn) {
#pragma unroll
    for (int i = 0; i < 2; i++)
#pragma unroll
        for (int j = 0; j < 2; j++)
            wmma::store_matrix_sync(&smem[(wm * 32 + i * 16) * LDC + wn * 32 + j * 16],
                                    acc[i][j], LDC, wmma::mem_row_major);
}

__device__ __forceinline__ float relu_t32(float v, float b) {
    return wmma::__float_to_tf32(fmaxf(v + b, 0.f));
}

// ---------------------------------------------------------------------------
// conv1 TF32 WMMA (r11 proven): M=1638400, N=32, K=64. Epilogue now rounds.
// ---------------------------------------------------------------------------
__global__ __launch_bounds__(256) void conv1_wmma_kernel(const float* __restrict__ x,
                                                         const float* __restrict__ b1) {
    __shared__ float smem[5504];
    const int tid = threadIdx.x;
    const int wid = tid >> 5, wm = wid >> 1, wn = wid & 1;
    const int m0 = blockIdx.x * 128;
    const int ar = tid >> 1, q = tid & 1;
    const int m = m0 + ar;
    const int an = m / 400, ap = m % 400;
    const int iy = (ap / 20) * 4, ix = (ap % 20) * 4;
    const float* xrow = x + (size_t)an * 7056 + ix;
    const int kb = tid >> 3, ob = (tid & 7) << 2;

    AccFrag acc1[2];
#pragma unroll
    for (int i = 0; i < 2; i++) wmma::fill_fragment(acc1[i], 0.f);

    float* As = smem;
    float* Bs = smem + 4352;

#define C1_LOADA(k0, v0, v1)                                   \
    {                                                          \
        const int ky = ((k0) >> 3) + q;                        \
        const float* xp = xrow + (iy + ky) * 84;               \
        v0 = *(const float4*)(xp);                             \
        v1 = *(const float4*)(xp + 4);                         \
    }

    {
        float4 a0, a1;
        C1_LOADA(0, a0, a1);
        float4 bv;
        if (tid < 128) bv = *(const float4*)&g_w1t[kb * 32 + ob];
        STAGE_A8C(As, ar, q * 8, a0, a1);
        if (tid < 128) *(float4*)&Bs[kb * LDB1 + ob] = bv;
    }
    __syncthreads();

    int buf = 0;
    for (int k0 = 16; k0 < 64; k0 += 16) {
        float4 a0, a1;
        C1_LOADA(k0, a0, a1);
        float4 bv;
        if (tid < 128) bv = *(const float4*)&g_w1t[(k0 + kb) * 32 + ob];
#pragma unroll
        for (int ks = 0; ks < 16; ks += 8) {
            AFrag a[2]; BFrag b;
#pragma unroll
            for (int i = 0; i < 2; i++)
                wmma::load_matrix_sync(a[i], As + buf * 2176 + ks * LDA + wm * 32 + i * 16, LDA);
            wmma::load_matrix_sync(b, Bs + buf * 576 + ks * LDB1 + wn * 16, LDB1);
#pragma unroll
            for (int i = 0; i < 2; i++)
                wmma::mma_sync(acc1[i], a[i], b, acc1[i]);
        }
        float* An = As + (buf ^ 1) * 2176;
        float* Bn = Bs + (buf ^ 1) * 576;
        STAGE_A8C(An, ar, q * 8, a0, a1);
        if (tid < 128) *(float4*)&Bn[kb * LDB1 + ob] = bv;
        __syncthreads();
        buf ^= 1;
    }
#pragma unroll
    for (int ks = 0; ks < 16; ks += 8) {
        AFrag a[2]; BFrag b;
#pragma unroll
        for (int i = 0; i < 2; i++)
            wmma::load_matrix_sync(a[i], As + buf * 2176 + ks * LDA + wm * 32 + i * 16, LDA);
        wmma::load_matrix_sync(b, Bs + buf * 576 + ks * LDB1 + wn * 16, LDB1);
#pragma unroll
        for (int i = 0; i < 2; i++)
            wmma::mma_sync(acc1[i], a[i], b, acc1[i]);
    }
    __syncthreads();
#pragma unroll
    for (int i = 0; i < 2; i++)
        wmma::store_matrix_sync(&smem[(wm * 32 + i * 16) * LDC1 + wn * 16], acc1[i],
                                LDC1, wmma::mem_row_major);
    __syncthreads();

    const int r = tid >> 1, h = tid & 1;
    const int rn = (m0 + r) / 400, rp = (m0 + r) % 400;
#pragma unroll
    for (int j = 0; j < 2; j++) {
        const int oc4 = h * 16 + j * 8;
#pragma unroll
        for (int s = 0; s < 2; s++) {
            const int oc = oc4 + s * 4;
            const float4 v = *(float4*)&smem[r * LDC1 + oc];
            const float4 bb = *(const float4*)&b1[oc];
            float4 o;
            o.x = relu_t32(v.x, bb.x);
            o.y = relu_t32(v.y, bb.y);
            o.z = relu_t32(v.z, bb.z);
            o.w = relu_t32(v.w, bb.w);
            const int g = oc >> 3, l = oc & 7;
            *(float4*)&g_z1[((size_t)rn * 4 + g) * 3200 + rp * 8 + l] = o;
        }
    }
}

// ---------------------------------------------------------------------------
// conv2 TF32 (r11 skeleton, raw A staging): M=331776, K=512, N=64.
// ---------------------------------------------------------------------------
__global__ __launch_bounds__(256) void conv2_wmma_kernel(const float* __restrict__ b2) {
    __shared__ float smem[9216];
    const int tid = threadIdx.x;
    const int wid = tid >> 5, wm = wid >> 1, wn = wid & 1;
    const int m0 = blockIdx.x * 128;
    const int ar = tid >> 1, q = tid & 1;
    const int m = m0 + ar;
    const int an = m / 81, ap = m % 81;
    const int aiy = (ap / 9) * 2, aix = (ap % 9) * 2;
    const int kb = tid >> 4, ob = (tid & 15) << 2;

    AccFrag acc[2][2];
#pragma unroll
    for (int i = 0; i < 2; i++)
#pragma unroll
        for (int j = 0; j < 2; j++) wmma::fill_fragment(acc[i][j], 0.f);

    float* As = smem;
    float* Bs = smem + 4352;

#define C2_LOADA(k0, v0, v1)                                                     \
    {                                                                            \
        const int g = ((k0) >> 3) + q;                                           \
        const int c = g >> 4, k16 = g & 15;                                      \
        const int ky = k16 >> 2, kx = k16 & 3;                                   \
        const float* p = &g_z1[(((size_t)an * 4 + c) * 400 +                     \
                                (aiy + ky) * 20 + aix + kx) * 8];                \
        v0 = *(const float4*)p; v1 = *(const float4*)(p + 4);                    \
    }

    {
        float4 a0, a1;
        C2_LOADA(0, a0, a1);
        const float4 bv = *(const float4*)&g_w2t[(size_t)kb * 64 + ob];
        STAGE_A8(As, ar, q * 8, a0, a1);
        *(float4*)&Bs[kb * LDB + ob] = bv;
    }
    __syncthreads();

    int buf = 0;
    for (int k0 = 16; k0 < 512; k0 += 16) {
        float4 a0, a1;
        C2_LOADA(k0, a0, a1);
        const float4 bv = *(const float4*)&g_w2t[(size_t)(k0 + kb) * 64 + ob];
        mma_chunk(As + buf * 2176, Bs + buf * 1152, acc, wm, wn);
        float* An = As + (buf ^ 1) * 2176;
        float* Bn = Bs + (buf ^ 1) * 1152;
        STAGE_A8(An, ar, q * 8, a0, a1);
        *(float4*)&Bn[kb * LDB + ob] = bv;
        __syncthreads();
        buf ^= 1;
    }
    mma_chunk(As + buf * 2176, Bs + buf * 1152, acc, wm, wn);
    __syncthreads();
    store_c_frags(smem, acc, wm, wn);
    __syncthreads();

    const int r = tid >> 1, h = tid & 1;
    const int rn = (m0 + r) / 81, rp = (m0 + r) % 81;
#pragma unroll
    for (int j = 0; j < 8; j++) {
        const int oc = h * 32 + j * 4;
        const float4 v = *(float4*)&smem[r * LDC + oc];
        const float4 bb = *(const float4*)&b2[oc];
        float4 o;
        o.x = relu_t32(v.x, bb.x);
        o.y = relu_t32(v.y, bb.y);
        o.z = relu_t32(v.z, bb.z);
        o.w = relu_t32(v.w, bb.w);
        *(float4*)&g_z2[(((size_t)rn * 4 + (oc >> 4)) * 81 + rp) * 16 + (oc & 15)] = o;
    }
}

// ---------------------------------------------------------------------------
// conv3 TF32 (r11 skeleton, raw A staging): M=200704, K=576, N=64.
// ---------------------------------------------------------------------------
__global__ __launch_bounds__(256) void conv3_wmma_kernel(const float* __restrict__ b3) {
    __shared__ float smem[9216];
    const int tid = threadIdx.x;
    const int wid = tid >> 5, wm = wid >> 1, wn = wid & 1;
    const int m0 = blockIdx.x * 128;
    const int ar = tid >> 1, q = tid & 1;
    const int m = m0 + ar;
    const int an = m / 49, ap = m % 49;
    const int aoy = ap / 7, aox = ap % 7;
    const int kb = tid >> 4, ob = (tid & 15) << 2;

    AccFrag acc[2][2];
#pragma unroll
    for (int i = 0; i < 2; i++)
#pragma unroll
        for (int j = 0; j < 2; j++) wmma::fill_fragment(acc[i][j], 0.f);

    float* As = smem;
    float* Bs = smem + 4352;

#define C3_LOADA(k0, v0, v1)                                                     \
    {                                                                            \
        const int g = (k0) >> 4;                                                 \
        const int icc = g / 9, k9 = g % 9;                                       \
        const int ky = k9 / 3, kx = k9 % 3;                                      \
        const float* p = &g_z2[(((size_t)an * 4 + icc) * 81 +                    \
                                (aoy + ky) * 9 + aox + kx) * 16 + q * 8];        \
        v0 = *(const float4*)p; v1 = *(const float4*)(p + 4);                    \
    }

    {
        float4 a0, a1;
        C3_LOADA(0, a0, a1);
        const float4 bv = *(const float4*)&g_w3t[(size_t)kb * 64 + ob];
        STAGE_A8(As, ar, q * 8, a0, a1);
        *(float4*)&Bs[kb * LDB + ob] = bv;
    }
    __syncthreads();

    int buf = 0;
    for (int k0 = 16; k0 < 576; k0 += 16) {
        float4 a0, a1;
        C3_LOADA(k0, a0, a1);
        const float4 bv = *(const float4*)&g_w3t[(size_t)(k0 + kb) * 64 + ob];
        mma_chunk(As + buf * 2176, Bs + buf * 1152, acc, wm, wn);
        float* An = As + (buf ^ 1) * 2176;
        float* Bn = Bs + (buf ^ 1) * 1152;
        STAGE_A8(An, ar, q * 8, a0, a1);
        *(float4*)&Bn[kb * LDB + ob] = bv;
        __syncthreads();
        buf ^= 1;
    }
    mma_chunk(As + buf * 2176, Bs + buf * 1152, acc, wm, wn);
    __syncthreads();
    store_c_frags(smem, acc, wm, wn);
    __syncthreads();

    const int r = tid >> 1, h = tid & 1;
    const int rn = (m0 + r) / 49, rp = (m0 + r) % 49;
#pragma unroll
    for (int j = 0; j < 8; j++) {
        const int oc = h * 32 + j * 4;
        const float4 v = *(float4*)&smem[r * LDC + oc];
        const float4 bb = *(const float4*)&b3[oc];
        float* zp = &g_z3[(size_t)rn * 3136 + oc * 49 + rp];
        zp[0]   = relu_t32(v.x, bb.x);
        zp[49]  = relu_t32(v.y, bb.y);
        zp[98]  = relu_t32(v.z, bb.z);
        zp[147] = relu_t32(v.w, bb.w);
    }
}

// ---------------------------------------------------------------------------
// Dense TF32 GEMM (fc / gates): A pre-rounded, B from [k][n] transposed weights.
// round_out: tf32-round the stored C (fc only; its output feeds gates' A).
// ---------------------------------------------------------------------------
__device__ __forceinline__ void gemm_wmma(const float* __restrict__ A,
                                          const float* __restrict__ Bt,  // [k][512]
                                          float* __restrict__ C, int K,
                                          const float* __restrict__ bias1,
                                          const float* __restrict__ bias2,
                                          bool relu, bool round_out) {
    __shared__ float smem[9216];
    const int tid = threadIdx.x;
    const int wid = tid >> 5, wm = wid >> 1, wn = wid & 1;
    const int m0 = blockIdx.y * 128, n0 = blockIdx.x * 64;
    const int ar = tid >> 1, q = tid & 1;
    const int kb = tid >> 4, ob = (tid & 15) << 2;
    const float* Ap = A + (size_t)(m0 + ar) * K + q * 8;
    const float* Btp = Bt + n0 + ob;

    AccFrag acc[2][2];
#pragma unroll
    for (int i = 0; i < 2; i++)
#pragma unroll
        for (int j = 0; j < 2; j++) wmma::fill_fragment(acc[i][j], 0.f);

    float* As = smem;
    float* Bs = smem + 4352;

    {
        const float4 a0 = *(const float4*)(Ap);
        const float4 a1 = *(const float4*)(Ap + 4);
        const float4 bv = *(const float4*)&Btp[(size_t)kb * 512];
        STAGE_A8(As, ar, q * 8, a0, a1);
        *(float4*)&Bs[kb * LDB + ob] = bv;
    }
    __syncthreads();

    int buf = 0;
    for (int k0 = 16; k0 < K; k0 += 16) {
        const float4 a0 = *(const float4*)(Ap + k0);
        const float4 a1 = *(const float4*)(Ap + k0 + 4);
        const float4 bv = *(const float4*)&Btp[(size_t)(k0 + kb) * 512];
        mma_chunk(As + buf * 2176, Bs + buf * 1152, acc, wm, wn);
        float* An = As + (buf ^ 1) * 2176;
        float* Bn = Bs + (buf ^ 1) * 1152;
        STAGE_A8(An, ar, q * 8, a0, a1);
        *(float4*)&Bn[kb * LDB + ob] = bv;
        __syncthreads();
        buf ^= 1;
    }
    mma_chunk(As + buf * 2176, Bs + buf * 1152, acc, wm, wn);
    __syncthreads();
    store_c_frags(smem, acc, wm, wn);
    __syncthreads();

    const int r = tid >> 1, h = tid & 1;
#pragma unroll
    for (int j = 0; j < 8; j++) {
        const int c = h * 32 + j * 4;
        float4 v = *(float4*)&smem[r * LDC + c];
        const float b0 = bias1[n0 + c + 0] + (bias2 ? bias2[n0 + c + 0] : 0.f);
        const float b1v = bias1[n0 + c + 1] + (bias2 ? bias2[n0 + c + 1] : 0.f);
        const float b2v = bias1[n0 + c + 2] + (bias2 ? bias2[n0 + c + 2] : 0.f);
        const float b3v = bias1[n0 + c + 3] + (bias2 ? bias2[n0 + c + 3] : 0.f);
        v.x += b0; v.y += b1v; v.z += b2v; v.w += b3v;
        if (relu) {
            v.x = fmaxf(v.x, 0.f); v.y = fmaxf(v.y, 0.f);
            v.z = fmaxf(v.z, 0.f); v.w = fmaxf(v.w, 0.f);
        }
        if (round_out) {
            v.x = wmma::__float_to_tf32(v.x);
            v.y = wmma::__float_to_tf32(v.y);
            v.z = wmma::__float_to_tf32(v.z);
            v.w = wmma::__float_to_tf32(v.w);
        }
        *(float4*)&C[(size_t)(m0 + r) * 512 + n0 + c] = v;
    }
}

__global__ __launch_bounds__(256) void fc_gemm_kernel(const float* __restrict__ bfc) {
    gemm_wmma(g_z3, g_wfcT, g_hidden, 3136, bfc, nullptr, true, true);
}
__global__ __launch_bounds__(256) void gates_gemm_kernel(const float* __restrict__ b_ih,
                                                         const float* __restrict__ b_hh) {
    gemm_wmma(g_hidden, g_wihT, g_gates, 512, b_ih, b_hh, false, false);
}

// ---------------------------------------------------------------------------
// LSTM: one block per batch element, 512 threads (proven coalesced, fp32).
// ---------------------------------------------------------------------------
__device__ __forceinline__ float sigmoidf_(float v) {
    return 1.0f / (1.0f + __expf(-v));
}

__global__ __launch_bounds__(512) void lstm_kernel(const float* __restrict__ done,
                                                   const float* __restrict__ h0,
                                                   const float* __restrict__ c0,
                                                   float* __restrict__ out) {
    __shared__ float hm[HID];
    __shared__ float cs[HID];
    __shared__ float hs[HID];
    __shared__ float part[4 * 512];
    const int b = blockIdx.x;
    const int tid = threadIdx.x;
    const int j4 = tid & 127;
    const int ks = tid >> 7;

    if (tid < HID) {
        hs[tid] = h0[b * HID + tid];
        cs[tid] = c0[b * HID + tid];
    }
    __syncthreads();

    for (int t = 0; t < TSTEPS; t++) {
        const float mask = 1.0f - done[t * BATCH + b];
        if (tid < HID) hm[tid] = hs[tid] * mask;
        __syncthreads();

        float a0 = 0.f, a1 = 0.f, a2 = 0.f, a3 = 0.f;
        const float4* __restrict__ wt = (const float4*)&g_whhT[(ks * 32) * 512] + j4;
        const float* __restrict__ hk = &hm[ks * 32];
#pragma unroll
        for (int kk = 0; kk < 32; kk++) {
            const float4 w = wt[kk * 128];
            const float h = hk[kk];
            a0 += w.x * h; a1 += w.y * h; a2 += w.z * h; a3 += w.w * h;
        }
        float4 pv = {a0, a1, a2, a3};
        *(float4*)&part[ks * 512 + j4 * 4] = pv;
        __syncthreads();

        const float gx = g_gates[(size_t)(t * BATCH + b) * 512 + tid];
        const float gsum = part[tid] + part[512 + tid] + part[1024 + tid] +
                           part[1536 + tid] + gx;
        part[tid] = gsum;
        __syncthreads();

        if (tid < HID) {
            const float gi = part[tid];
            const float gf = part[tid + 128];
            const float gc = part[tid + 256];
            const float go = part[tid + 384];
            float c = cs[tid] * mask;
            c = sigmoidf_(gf) * c + sigmoidf_(gi) * tanhf(gc);
            const float h = sigmoidf_(go) * tanhf(c);
            cs[tid] = c;
            hs[tid] = h;
            g_hs[(size_t)(t * BATCH + b) * HID + tid] = h;
            if (t == TSTEPS - 1) {
                out[28672 + b * HID + tid] = h;
                out[32768 + b * HID + tid] = c;
            }
        }
        __syncthreads();
    }
}

// ---------------------------------------------------------------------------
// Heads: logits (4096x6) and value (4096x1) from g_hs.
// ---------------------------------------------------------------------------
__global__ __launch_bounds__(256) void heads_kernel(const float* __restrict__ Wa,
                                                    const float* __restrict__ ba,
                                                    const float* __restrict__ Wc,
                                                    const float* __restrict__ bc,
                                                    float* __restrict__ out) {
    __shared__ float was[6 * 128];
    __shared__ float wcs[128];
    __shared__ float bas[6];
    __shared__ float bcs;
    const int tid = threadIdx.x;
    for (int i = tid; i < 768; i += 256) was[i] = Wa[i];
    if (tid < 128) wcs[tid] = Wc[tid];
    if (tid < 6) bas[tid] = ba[tid];
    if (tid == 0) bcs = bc[0];
    __syncthreads();

    const int row = blockIdx.x * 256 + tid;
    const float* hp = &g_hs[(size_t)row * 128];
    float acc[6] = {0.f, 0.f, 0.f, 0.f, 0.f, 0.f};
    float accv = 0.f;
    for (int k = 0; k < 128; k += 4) {
        const float4 h4 = *(const float4*)&hp[k];
#pragma unroll
        for (int a = 0; a < 6; a++) {
            const float4 w4 = *(const float4*)&was[a * 128 + k];
            acc[a] += h4.x * w4.x + h4.y * w4.y + h4.z * w4.z + h4.w * w4.w;
        }
        const float4 wc4 = *(const float4*)&wcs[k];
        accv += h4.x * wc4.x + h4.y * wc4.y + h4.z * wc4.z + h4.w * wc4.w;
    }
#pragma unroll
    for (int a = 0; a < 6; a++) out[row * 6 + a] = acc[a] + bas[a];
    out[24576 + row] = accv + bcs;
}

// ---------------------------------------------------------------------------
// Launch
// ---------------------------------------------------------------------------
extern "C" void kernel_launch(void* const* d_in, const int* in_sizes, int n_in,
                              void* d_out, int out_size) {
    const float* x    = (const float*)d_in[0];
    const float* done = (const float*)d_in[1];
    const float* h0   = (const float*)d_in[2];
    const float* c0   = (const float*)d_in[3];
    const float* W1   = (const float*)d_in[4];
    const float* b1   = (const float*)d_in[5];
    const float* W2   = (const float*)d_in[6];
    const float* b2   = (const float*)d_in[7];
    const float* W3   = (const float*)d_in[8];
    const float* b3   = (const float*)d_in[9];
    const float* Wfc  = (const float*)d_in[10];
    const float* bfc  = (const float*)d_in[11];
    const float* W_ih = (const float*)d_in[12];
    const float* W_hh = (const float*)d_in[13];
    const float* b_ih = (const float*)d_in[14];
    const float* b_hh = (const float*)d_in[15];
    const float* Wa   = (const float*)d_in[16];
    const float* ba   = (const float*)d_in[17];
    const float* Wc   = (const float*)d_in[18];
    const float* bc   = (const float*)d_in[19];
    float* out = (float*)d_out;

    whh_transpose_kernel<<<128, 512>>>(W_hh);
    w1t_kernel<<<8, 256>>>(W1);
    w2t_kernel<<<128, 256>>>(W2);
    w3t_kernel<<<144, 256>>>(W3);
    wfct_kernel<<<6272, 256>>>(Wfc);
    wiht_kernel<<<1024, 256>>>(W_ih);
    conv1_wmma_kernel<<<12800, 256>>>(x, b1);
    conv2_wmma_kernel<<<2592, 256>>>(b2);
    conv3_wmma_kernel<<<1568, 256>>>(b3);
    fc_gemm_kernel<<<dim3(8, 32), 256>>>(bfc);
    gates_gemm_kernel<<<dim3(8, 32), 256>>>(b_ih, b_hh);
    lstm_kernel<<<BATCH, 512>>>(done, h0, c0, out);
    heads_kernel<<<16, 256>>>(Wa, ba, Wc, bc, out);
}

// round 15
// speedup vs baseline: 1.1946x; 1.0675x over previous
#include <cuda_runtime.h>
#include <mma.h>
#include <cstdint>

using namespace nvcuda;

#define NIMG   4096
#define TSTEPS 128
#define BATCH  32
#define HID    128

// Scratch (device globals; no allocation allowed)
__device__ float g_z1[(size_t)NIMG * 4 * 400 * 8];    // conv1 out (tf32-rounded)
__device__ float g_z2[(size_t)NIMG * 4 * 81 * 16];    // conv2 out (tf32-rounded)
__device__ float g_z3[(size_t)NIMG * 3136];           // conv3 out (tf32-rounded)
__device__ float g_hidden[(size_t)NIMG * 512];        // FC out (tf32-rounded)
__device__ float g_gates[(size_t)NIMG * 512];         // x-proj of gates (fp32)
__device__ float g_hs[(size_t)NIMG * HID];            // per-step hidden outputs
__device__ float g_whhT[HID * 512];                   // W_hh transposed
__device__ float g_w1t[64 * 32];                      // W1/255 [k][oc] (tf32)
__device__ float g_w2t[512 * 64];                     // W2 [k][oc] (tf32)
__device__ float g_w3t[576 * 64];                     // W3 [k][oc] (tf32)
__device__ float g_wfcT[3136 * 512];                  // Wfc [k][n] (tf32)
__device__ float g_wihT[512 * 512];                   // W_ih [k][n] (tf32)

// ---------------------------------------------------------------------------
// cp.async helpers
// ---------------------------------------------------------------------------
__device__ __forceinline__ unsigned smem_u32(const void* p) {
    return (unsigned)__cvta_generic_to_shared(p);
}
#define CP16(dst, src) \
    asm volatile("cp.async.ca.shared.global [%0], [%1], 16;" \
                 :: "r"(smem_u32(dst)), "l"(src) : "memory")
#define CP_COMMIT() asm volatile("cp.async.commit_group;" ::: "memory")
#define CP_WAIT0()  asm volatile("cp.async.wait_group 0;" ::: "memory")

// ---------------------------------------------------------------------------
// Weight re-layout preps (all tf32-rounded)
// ---------------------------------------------------------------------------
__global__ __launch_bounds__(256) void w1t_kernel(const float* __restrict__ W1) {
    const int id = blockIdx.x * 256 + threadIdx.x;
    const int k = id >> 5, oc = id & 31;
    g_w1t[k * 32 + oc] = wmma::__float_to_tf32(W1[oc * 64 + k] * (1.0f / 255.0f));
}
__global__ __launch_bounds__(256) void w2t_kernel(const float* __restrict__ W2) {
    const int id = blockIdx.x * 256 + threadIdx.x;
    const int k = id >> 6, oc = id & 63;
    const int c = k >> 7, k16 = (k & 127) >> 3, icl = k & 7;
    g_w2t[k * 64 + oc] = wmma::__float_to_tf32(W2[oc * 512 + (c * 8 + icl) * 16 + k16]);
}
__global__ __launch_bounds__(256) void w3t_kernel(const float* __restrict__ W3) {
    const int id = blockIdx.x * 256 + threadIdx.x;
    const int k = id >> 6, oc = id & 63;
    const int icc = k / 144, rem = k % 144, k9 = rem >> 4, icl = rem & 15;
    g_w3t[k * 64 + oc] = wmma::__float_to_tf32(W3[oc * 576 + (icc * 16 + icl) * 9 + k9]);
}
__global__ __launch_bounds__(256) void wfct_kernel(const float* __restrict__ Wfc) {
    const int id = blockIdx.x * 256 + threadIdx.x;   // 0..1605631
    const int k = id >> 9, n = id & 511;
    g_wfcT[(size_t)k * 512 + n] = wmma::__float_to_tf32(Wfc[(size_t)n * 3136 + k]);
}
__global__ __launch_bounds__(256) void wiht_kernel(const float* __restrict__ W_ih) {
    const int id = blockIdx.x * 256 + threadIdx.x;   // 0..262143
    const int k = id >> 9, n = id & 511;
    g_wihT[k * 512 + n] = wmma::__float_to_tf32(W_ih[n * 512 + k]);
}
__global__ __launch_bounds__(512) void whh_transpose_kernel(const float* __restrict__ W_hh) {
    const int id = blockIdx.x * 512 + threadIdx.x;
    const int k = id >> 9, j = id & 511;
    g_whhT[k * 512 + j] = W_hh[j * 128 + k];
}

// ---------------------------------------------------------------------------
// Common WMMA defs
// ---------------------------------------------------------------------------
#define LDA 136     // conv1 col-major A
#define LDAR 24     // row-major A pad (multiple of 4, breaks bank repeat)
#define LDB 72
#define LDC 72
#define LDB1 36
#define LDC1 36

typedef wmma::fragment<wmma::accumulator, 16, 16, 8, float> AccFrag;
typedef wmma::fragment<wmma::matrix_a, 16, 16, 8, wmma::precision::tf32, wmma::col_major> AFrag;
typedef wmma::fragment<wmma::matrix_a, 16, 16, 8, wmma::precision::tf32, wmma::row_major> AFragR;
typedef wmma::fragment<wmma::matrix_b, 16, 16, 8, wmma::precision::tf32, wmma::row_major> BFrag;

// converting copy (external input, conv1 only)
#define STAGE_A8C(dst, ar, kb, v0, v1)                                \
    {                                                                 \
        (dst)[((kb) + 0) * LDA + (ar)] = wmma::__float_to_tf32(v0.x); \
        (dst)[((kb) + 1) * LDA + (ar)] = wmma::__float_to_tf32(v0.y); \
        (dst)[((kb) + 2) * LDA + (ar)] = wmma::__float_to_tf32(v0.z); \
        (dst)[((kb) + 3) * LDA + (ar)] = wmma::__float_to_tf32(v0.w); \
        (dst)[((kb) + 4) * LDA + (ar)] = wmma::__float_to_tf32(v1.x); \
        (dst)[((kb) + 5) * LDA + (ar)] = wmma::__float_to_tf32(v1.y); \
        (dst)[((kb) + 6) * LDA + (ar)] = wmma::__float_to_tf32(v1.z); \
        (dst)[((kb) + 7) * LDA + (ar)] = wmma::__float_to_tf32(v1.w); \
    }

// row-major-A mma chunk (16 k): As[128][LDAR], Bs[16][LDB]
__device__ __forceinline__ void mma_chunkR(const float* __restrict__ As,
                                           const float* __restrict__ Bs,
                                           AccFrag (&acc)[2][2], int wm, int wn) {
#pragma unroll
    for (int ks = 0; ks < 16; ks += 8) {
        AFragR a[2]; BFrag b[2];
#pragma unroll
        for (int i = 0; i < 2; i++)
            wmma::load_matrix_sync(a[i], As + (wm * 32 + i * 16) * LDAR + ks, LDAR);
#pragma unroll
        for (int j = 0; j < 2; j++)
            wmma::load_matrix_sync(b[j], Bs + ks * LDB + wn * 32 + j * 16, LDB);
#pragma unroll
        for (int i = 0; i < 2; i++)
#pragma unroll
            for (int j = 0; j < 2; j++)
                wmma::mma_sync(acc[i][j], a[i], b[j], acc[i][j]);
    }
}

__device__ __forceinline__ void store_c_frags(float* smem, AccFrag (&acc)[2][2],
                                              int wm, int wn) {
#pragma unroll
    for (int i = 0; i < 2; i++)
#pragma unroll
        for (int j = 0; j < 2; j++)
            wmma::store_matrix_sync(&smem[(wm * 32 + i * 16) * LDC + wn * 32 + j * 16],
                                    acc[i][j], LDC, wmma::mem_row_major);
}

__device__ __forceinline__ float relu_t32(float v, float b) {
    return wmma::__float_to_tf32(fmaxf(v + b, 0.f));
}

// smem layout for cp.async kernels (floats):
// As: 2 x 128*24 = 6144 @0 ; Bs: 2 x 16*72 = 2304 @6144 ; epilogue C [128][72] @0
#define ASR(sm, buf) ((sm) + (buf) * 3072)
#define BSR(sm, buf) ((sm) + 6144 + (buf) * 1152)
#define SMEM_FLOATS 11520

// ---------------------------------------------------------------------------
// conv1 TF32 WMMA (r11/r14 proven): M=1638400, N=32, K=64.
// ---------------------------------------------------------------------------
__global__ __launch_bounds__(256) void conv1_wmma_kernel(const float* __restrict__ x,
                                                         const float* __restrict__ b1) {
    __shared__ float smem[5504];
    const int tid = threadIdx.x;
    const int wid = tid >> 5, wm = wid >> 1, wn = wid & 1;
    const int m0 = blockIdx.x * 128;
    const int ar = tid >> 1, q = tid & 1;
    const int m = m0 + ar;
    const int an = m / 400, ap = m % 400;
    const int iy = (ap / 20) * 4, ix = (ap % 20) * 4;
    const float* xrow = x + (size_t)an * 7056 + ix;
    const int kb = tid >> 3, ob = (tid & 7) << 2;

    AccFrag acc1[2];
#pragma unroll
    for (int i = 0; i < 2; i++) wmma::fill_fragment(acc1[i], 0.f);

    float* As = smem;
    float* Bs = smem + 4352;

#define C1_LOADA(k0, v0, v1)                                   \
    {                                                          \
        const int ky = ((k0) >> 3) + q;                        \
        const float* xp = xrow + (iy + ky) * 84;               \
        v0 = *(const float4*)(xp);                             \
        v1 = *(const float4*)(xp + 4);                         \
    }

    {
        float4 a0, a1;
        C1_LOADA(0, a0, a1);
        float4 bv;
        if (tid < 128) bv = *(const float4*)&g_w1t[kb * 32 + ob];
        STAGE_A8C(As, ar, q * 8, a0, a1);
        if (tid < 128) *(float4*)&Bs[kb * LDB1 + ob] = bv;
    }
    __syncthreads();

    int buf = 0;
    for (int k0 = 16; k0 < 64; k0 += 16) {
        float4 a0, a1;
        C1_LOADA(k0, a0, a1);
        float4 bv;
        if (tid < 128) bv = *(const float4*)&g_w1t[(k0 + kb) * 32 + ob];
#pragma unroll
        for (int ks = 0; ks < 16; ks += 8) {
            AFrag a[2]; BFrag b;
#pragma unroll
            for (int i = 0; i < 2; i++)
                wmma::load_matrix_sync(a[i], As + buf * 2176 + ks * LDA + wm * 32 + i * 16, LDA);
            wmma::load_matrix_sync(b, Bs + buf * 576 + ks * LDB1 + wn * 16, LDB1);
#pragma unroll
            for (int i = 0; i < 2; i++)
                wmma::mma_sync(acc1[i], a[i], b, acc1[i]);
        }
        float* An = As + (buf ^ 1) * 2176;
        float* Bn = Bs + (buf ^ 1) * 576;
        STAGE_A8C(An, ar, q * 8, a0, a1);
        if (tid < 128) *(float4*)&Bn[kb * LDB1 + ob] = bv;
        __syncthreads();
        buf ^= 1;
    }
#pragma unroll
    for (int ks = 0; ks < 16; ks += 8) {
        AFrag a[2]; BFrag b;
#pragma unroll
        for (int i = 0; i < 2; i++)
            wmma::load_matrix_sync(a[i], As + buf * 2176 + ks * LDA + wm * 32 + i * 16, LDA);
        wmma::load_matrix_sync(b, Bs + buf * 576 + ks * LDB1 + wn * 16, LDB1);
#pragma unroll
        for (int i = 0; i < 2; i++)
            wmma::mma_sync(acc1[i], a[i], b, acc1[i]);
    }
    __syncthreads();
#pragma unroll
    for (int i = 0; i < 2; i++)
        wmma::store_matrix_sync(&smem[(wm * 32 + i * 16) * LDC1 + wn * 16], acc1[i],
                                LDC1, wmma::mem_row_major);
    __syncthreads();

    const int r = tid >> 1, h = tid & 1;
    const int rn = (m0 + r) / 400, rp = (m0 + r) % 400;
#pragma unroll
    for (int j = 0; j < 2; j++) {
        const int oc4 = h * 16 + j * 8;
#pragma unroll
        for (int s = 0; s < 2; s++) {
            const int oc = oc4 + s * 4;
            const float4 v = *(float4*)&smem[r * LDC1 + oc];
            const float4 bb = *(const float4*)&b1[oc];
            float4 o;
            o.x = relu_t32(v.x, bb.x);
            o.y = relu_t32(v.y, bb.y);
            o.z = relu_t32(v.z, bb.z);
            o.w = relu_t32(v.w, bb.w);
            const int g = oc >> 3, l = oc & 7;
            *(float4*)&g_z1[((size_t)rn * 4 + g) * 3200 + rp * 8 + l] = o;
        }
    }
}

// ---------------------------------------------------------------------------
// conv2 TF32 cp.async: M=331776, K=512, N=64.
// ---------------------------------------------------------------------------
__global__ __launch_bounds__(256) void conv2_wmma_kernel(const float* __restrict__ b2) {
    __shared__ float smem[SMEM_FLOATS];
    const int tid = threadIdx.x;
    const int wid = tid >> 5, wm = wid >> 1, wn = wid & 1;
    const int m0 = blockIdx.x * 128;
    const int ar = tid >> 1, q = tid & 1;
    const int m = m0 + ar;
    const int an = m / 81, ap = m % 81;
    const int aiy = (ap / 9) * 2, aix = (ap % 9) * 2;
    const int kb = tid >> 4, ob = (tid & 15) << 2;

    AccFrag acc[2][2];
#pragma unroll
    for (int i = 0; i < 2; i++)
#pragma unroll
        for (int j = 0; j < 2; j++) wmma::fill_fragment(acc[i][j], 0.f);

#define C2_CPA(buf, k0)                                                          \
    {                                                                            \
        const int g = ((k0) >> 3) + q;                                           \
        const int c = g >> 4, k16 = g & 15;                                      \
        const int ky = k16 >> 2, kx = k16 & 3;                                   \
        const float* p = &g_z1[(((size_t)an * 4 + c) * 400 +                     \
                                (aiy + ky) * 20 + aix + kx) * 8];                \
        float* d = &ASR(smem, buf)[ar * LDAR + q * 8];                           \
        CP16(d, p); CP16(d + 4, p + 4);                                          \
        CP16(&BSR(smem, buf)[kb * LDB + ob], &g_w2t[(size_t)((k0) + kb) * 64 + ob]); \
    }

    C2_CPA(0, 0);
    CP_COMMIT(); CP_WAIT0();
    __syncthreads();

    int buf = 0;
    for (int k0 = 16; k0 < 512; k0 += 16) {
        C2_CPA(buf ^ 1, k0);
        CP_COMMIT();
        mma_chunkR(ASR(smem, buf), BSR(smem, buf), acc, wm, wn);
        CP_WAIT0();
        __syncthreads();
        buf ^= 1;
    }
    mma_chunkR(ASR(smem, buf), BSR(smem, buf), acc, wm, wn);
    __syncthreads();
    store_c_frags(smem, acc, wm, wn);
    __syncthreads();

    const int r = tid >> 1, h = tid & 1;
    const int rn = (m0 + r) / 81, rp = (m0 + r) % 81;
#pragma unroll
    for (int j = 0; j < 8; j++) {
        const int oc = h * 32 + j * 4;
        const float4 v = *(float4*)&smem[r * LDC + oc];
        const float4 bb = *(const float4*)&b2[oc];
        float4 o;
        o.x = relu_t32(v.x, bb.x);
        o.y = relu_t32(v.y, bb.y);
        o.z = relu_t32(v.z, bb.z);
        o.w = relu_t32(v.w, bb.w);
        *(float4*)&g_z2[(((size_t)rn * 4 + (oc >> 4)) * 81 + rp) * 16 + (oc & 15)] = o;
    }
}

// ---------------------------------------------------------------------------
// conv3 TF32 cp.async: M=200704, K=576, N=64.
// ---------------------------------------------------------------------------
__global__ __launch_bounds__(256) void conv3_wmma_kernel(const float* __restrict__ b3) {
    __shared__ float smem[SMEM_FLOATS];
    const int tid = threadIdx.x;
    const int wid = tid >> 5, wm = wid >> 1, wn = wid & 1;
    const int m0 = blockIdx.x * 128;
    const int ar = tid >> 1, q = tid & 1;
    const int m = m0 + ar;
    const int an = m / 49, ap = m % 49;
    const int aoy = ap / 7, aox = ap % 7;
    const int kb = tid >> 4, ob = (tid & 15) << 2;

    AccFrag acc[2][2];
#pragma unroll
    for (int i = 0; i < 2; i++)
#pragma unroll
        for (int j = 0; j < 2; j++) wmma::fill_fragment(acc[i][j], 0.f);

#define C3_CPA(buf, k0)                                                          \
    {                                                                            \
        const int g = (k0) >> 4;                                                 \
        const int icc = g / 9, k9 = g % 9;                                       \
        const int ky = k9 / 3, kx = k9 % 3;                                      \
        const float* p = &g_z2[(((size_t)an * 4 + icc) * 81 +                    \
                                (aoy + ky) * 9 + aox + kx) * 16 + q * 8];        \
        float* d = &ASR(smem, buf)[ar * LDAR + q * 8];                           \
        CP16(d, p); CP16(d + 4, p + 4);                                          \
        CP16(&BSR(smem, buf)[kb * LDB + ob], &g_w3t[(size_t)((k0) + kb) * 64 + ob]); \
    }

    C3_CPA(0, 0);
    CP_COMMIT(); CP_WAIT0();
    __syncthreads();

    int buf = 0;
    for (int k0 = 16; k0 < 576; k0 += 16) {
        C3_CPA(buf ^ 1, k0);
        CP_COMMIT();
        mma_chunkR(ASR(smem, buf), BSR(smem, buf), acc, wm, wn);
        CP_WAIT0();
        __syncthreads();
        buf ^= 1;
    }
    mma_chunkR(ASR(smem, buf), BSR(smem, buf), acc, wm, wn);
    __syncthreads();
    store_c_frags(smem, acc, wm, wn);
    __syncthreads();

    const int r = tid >> 1, h = tid & 1;
    const int rn = (m0 + r) / 49, rp = (m0 + r) % 49;
#pragma unroll
    for (int j = 0; j < 8; j++) {
        const int oc = h * 32 + j * 4;
        const float4 v = *(float4*)&smem[r * LDC + oc];
        const float4 bb = *(const float4*)&b3[oc];
        float* zp = &g_z3[(size_t)rn * 3136 + oc * 49 + rp];
        zp[0]   = relu_t32(v.x, bb.x);
        zp[49]  = relu_t32(v.y, bb.y);
        zp[98]  = relu_t32(v.z, bb.z);
        zp[147] = relu_t32(v.w, bb.w);
    }
}

// ---------------------------------------------------------------------------
// Dense TF32 GEMM cp.async (fc / gates): B from [k][n] transposed weights.
// ---------------------------------------------------------------------------
__device__ __forceinline__ void gemm_wmma(const float* __restrict__ A,
                                          const float* __restrict__ Bt,  // [k][512]
                                          float* __restrict__ C, int K,
                                          const float* __restrict__ bias1,
                                          const float* __restrict__ bias2,
                                          bool relu, bool round_out) {
    __shared__ float smem[SMEM_FLOATS];
    const int tid = threadIdx.x;
    const int wid = tid >> 5, wm = wid >> 1, wn = wid & 1;
    const int m0 = blockIdx.y * 128, n0 = blockIdx.x * 64;
    const int ar = tid >> 1, q = tid & 1;
    const int kb = tid >> 4, ob = (tid & 15) << 2;
    const float* Ap = A + (size_t)(m0 + ar) * K + q * 8;
    const float* Btp = Bt + n0 + ob;

    AccFrag acc[2][2];
#pragma unroll
    for (int i = 0; i < 2; i++)
#pragma unroll
        for (int j = 0; j < 2; j++) wmma::fill_fragment(acc[i][j], 0.f);

#define G_CPA(buf, k0)                                                           \
    {                                                                            \
        const float* p = Ap + (k0);                                              \
        float* d = &ASR(smem, buf)[ar * LDAR + q * 8];                           \
        CP16(d, p); CP16(d + 4, p + 4);                                          \
        CP16(&BSR(smem, buf)[kb * LDB + ob], &Btp[(size_t)((k0) + kb) * 512]);   \
    }

    G_CPA(0, 0);
    CP_COMMIT(); CP_WAIT0();
    __syncthreads();

    int buf = 0;
    for (int k0 = 16; k0 < K; k0 += 16) {
        G_CPA(buf ^ 1, k0);
        CP_COMMIT();
        mma_chunkR(ASR(smem, buf), BSR(smem, buf), acc, wm, wn);
        CP_WAIT0();
        __syncthreads();
        buf ^= 1;
    }
    mma_chunkR(ASR(smem, buf), BSR(smem, buf), acc, wm, wn);
    __syncthreads();
    store_c_frags(smem, acc, wm, wn);
    __syncthreads();

    const int r = tid >> 1, h = tid & 1;
#pragma unroll
    for (int j = 0; j < 8; j++) {
        const int c = h * 32 + j * 4;
        float4 v = *(float4*)&smem[r * LDC + c];
        const float b0 = bias1[n0 + c + 0] + (bias2 ? bias2[n0 + c + 0] : 0.f);
        const float b1v = bias1[n0 + c + 1] + (bias2 ? bias2[n0 + c + 1] : 0.f);
        const float b2v = bias1[n0 + c + 2] + (bias2 ? bias2[n0 + c + 2] : 0.f);
        const float b3v = bias1[n0 + c + 3] + (bias2 ? bias2[n0 + c + 3] : 0.f);
        v.x += b0; v.y += b1v; v.z += b2v; v.w += b3v;
        if (relu) {
            v.x = fmaxf(v.x, 0.f); v.y = fmaxf(v.y, 0.f);
            v.z = fmaxf(v.z, 0.f); v.w = fmaxf(v.w, 0.f);
        }
        if (round_out) {
            v.x = wmma::__float_to_tf32(v.x);
            v.y = wmma::__float_to_tf32(v.y);
            v.z = wmma::__float_to_tf32(v.z);
            v.w = wmma::__float_to_tf32(v.w);
        }
        *(float4*)&C[(size_t)(m0 + r) * 512 + n0 + c] = v;
    }
}

__global__ __launch_bounds__(256) void fc_gemm_kernel(const float* __restrict__ bfc) {
    gemm_wmma(g_z3, g_wfcT, g_hidden, 3136, bfc, nullptr, true, true);
}
__global__ __launch_bounds__(256) void gates_gemm_kernel(const float* __restrict__ b_ih,
                                                         const float* __restrict__ b_hh) {
    gemm_wmma(g_hidden, g_wihT, g_gates, 512, b_ih, b_hh, false, false);
}

// ---------------------------------------------------------------------------
// LSTM: one block per batch element, 512 threads (proven coalesced, fp32).
// ---------------------------------------------------------------------------
__device__ __forceinline__ float sigmoidf_(float v) {
    return 1.0f / (1.0f + __expf(-v));
}

__global__ __launch_bounds__(512) void lstm_kernel(const float* __restrict__ done,
                                                   const float* __restrict__ h0,
                                                   const float* __restrict__ c0,
                                                   float* __restrict__ out) {
    __shared__ float hm[HID];
    __shared__ float cs[HID];
    __shared__ float hs[HID];
    __shared__ float part[4 * 512];
    const int b = blockIdx.x;
    const int tid = threadIdx.x;
    const int j4 = tid & 127;
    const int ks = tid >> 7;

    if (tid < HID) {
        hs[tid] = h0[b * HID + tid];
        cs[tid] = c0[b * HID + tid];
    }
    __syncthreads();

    for (int t = 0; t < TSTEPS; t++) {
        const float mask = 1.0f - done[t * BATCH + b];
        if (tid < HID) hm[tid] = hs[tid] * mask;
        __syncthreads();

        float a0 = 0.f, a1 = 0.f, a2 = 0.f, a3 = 0.f;
        const float4* __restrict__ wt = (const float4*)&g_whhT[(ks * 32) * 512] + j4;
        const float* __restrict__ hk = &hm[ks * 32];
#pragma unroll
        for (int kk = 0; kk < 32; kk++) {
            const float4 w = wt[kk * 128];
            const float h = hk[kk];
            a0 += w.x * h; a1 += w.y * h; a2 += w.z * h; a3 += w.w * h;
        }
        float4 pv = {a0, a1, a2, a3};
        *(float4*)&part[ks * 512 + j4 * 4] = pv;
        __syncthreads();

        const float gx = g_gates[(size_t)(t * BATCH + b) * 512 + tid];
        const float gsum = part[tid] + part[512 + tid] + part[1024 + tid] +
                           part[1536 + tid] + gx;
        part[tid] = gsum;
        __syncthreads();

        if (tid < HID) {
            const float gi = part[tid];
            const float gf = part[tid + 128];
            const float gc = part[tid + 256];
            const float go = part[tid + 384];
            float c = cs[tid] * mask;
            c = sigmoidf_(gf) * c + sigmoidf_(gi) * tanhf(gc);
            const float h = sigmoidf_(go) * tanhf(c);
            cs[tid] = c;
            hs[tid] = h;
            g_hs[(size_t)(t * BATCH + b) * HID + tid] = h;
            if (t == TSTEPS - 1) {
                out[28672 + b * HID + tid] = h;
                out[32768 + b * HID + tid] = c;
            }
        }
        __syncthreads();
    }
}

// ---------------------------------------------------------------------------
// Heads: logits (4096x6) and value (4096x1) from g_hs.
// ---------------------------------------------------------------------------
__global__ __launch_bounds__(256) void heads_kernel(const float* __restrict__ Wa,
                                                    const float* __restrict__ ba,
                                                    const float* __restrict__ Wc,
                                                    const float* __restrict__ bc,
                                                    float* __restrict__ out) {
    __shared__ float was[6 * 128];
    __shared__ float wcs[128];
    __shared__ float bas[6];
    __shared__ float bcs;
    const int tid = threadIdx.x;
    for (int i = tid; i < 768; i += 256) was[i] = Wa[i];
    if (tid < 128) wcs[tid] = Wc[tid];
    if (tid < 6) bas[tid] = ba[tid];
    if (tid == 0) bcs = bc[0];
    __syncthreads();

    const int row = blockIdx.x * 256 + tid;
    const float* hp = &g_hs[(size_t)row * 128];
    float acc[6] = {0.f, 0.f, 0.f, 0.f, 0.f, 0.f};
    float accv = 0.f;
    for (int k = 0; k < 128; k += 4) {
        const float4 h4 = *(const float4*)&hp[k];
#pragma unroll
        for (int a = 0; a < 6; a++) {
            const float4 w4 = *(const float4*)&was[a * 128 + k];
            acc[a] += h4.x * w4.x + h4.y * w4.y + h4.z * w4.z + h4.w * w4.w;
        }
        const float4 wc4 = *(const float4*)&wcs[k];
        accv += h4.x * wc4.x + h4.y * wc4.y + h4.z * wc4.z + h4.w * wc4.w;
    }
#pragma unroll
    for (int a = 0; a < 6; a++) out[row * 6 + a] = acc[a] + bas[a];
    out[24576 + row] = accv + bcs;
}

// ---------------------------------------------------------------------------
// Launch
// ---------------------------------------------------------------------------
extern "C" void kernel_launch(void* const* d_in, const int* in_sizes, int n_in,
                              void* d_out, int out_size) {
    const float* x    = (const float*)d_in[0];
    const float* done = (const float*)d_in[1];
    const float* h0   = (const float*)d_in[2];
    const float* c0   = (const float*)d_in[3];
    const float* W1   = (const float*)d_in[4];
    const float* b1   = (const float*)d_in[5];
    const float* W2   = (const float*)d_in[6];
    const float* b2   = (const float*)d_in[7];
    const float* W3   = (const float*)d_in[8];
    const float* b3   = (const float*)d_in[9];
    const float* Wfc  = (const float*)d_in[10];
    const float* bfc  = (const float*)d_in[11];
    const float* W_ih = (const float*)d_in[12];
    const float* W_hh = (const float*)d_in[13];
    const float* b_ih = (const float*)d_in[14];
    const float* b_hh = (const float*)d_in[15];
    const float* Wa   = (const float*)d_in[16];
    const float* ba   = (const float*)d_in[17];
    const float* Wc   = (const float*)d_in[18];
    const float* bc   = (const float*)d_in[19];
    float* out = (float*)d_out;

    whh_transpose_kernel<<<128, 512>>>(W_hh);
    w1t_kernel<<<8, 256>>>(W1);
    w2t_kernel<<<128, 256>>>(W2);
    w3t_kernel<<<144, 256>>>(W3);
    wfct_kernel<<<6272, 256>>>(Wfc);
    wiht_kernel<<<1024, 256>>>(W_ih);
    conv1_wmma_kernel<<<12800, 256>>>(x, b1);
    conv2_wmma_kernel<<<2592, 256>>>(b2);
    conv3_wmma_kernel<<<1568, 256>>>(b3);
    fc_gemm_kernel<<<dim3(8, 32), 256>>>(bfc);
    gates_gemm_kernel<<<dim3(8, 32), 256>>>(b_ih, b_hh);
    lstm_kernel<<<BATCH, 512>>>(done, h0, c0, out);
    heads_kernel<<<16, 256>>>(Wa, ba, Wc, bc, out);
}

// round 16
// speedup vs baseline: 1.2007x; 1.0051x over previous
#include <cuda_runtime.h>
#include <mma.h>
#include <cstdint>

using namespace nvcuda;

#define NIMG   4096
#define TSTEPS 128
#define BATCH  32
#define HID    128

// Scratch (device globals; no allocation allowed)
__device__ float g_z1[(size_t)NIMG * 4 * 400 * 8];    // conv1 out (tf32-rounded)
__device__ float g_z2[(size_t)NIMG * 4 * 81 * 16];    // conv2 out (tf32-rounded)
__device__ float g_z3[(size_t)NIMG * 3136];           // conv3 out (tf32-rounded)
__device__ float g_hidden[(size_t)NIMG * 512];        // FC out (tf32-rounded)
__device__ float g_gates[(size_t)NIMG * 512];         // x-proj of gates (fp32)
__device__ float g_hs[(size_t)NIMG * HID];            // per-step hidden outputs
__device__ float g_whhT[HID * 512];                   // W_hh transposed
__device__ float g_w1t[64 * 32];                      // W1/255 [k][oc] (tf32)
__device__ float g_w2t[512 * 64];                     // W2 [k][oc] (tf32)
__device__ float g_w3t[576 * 64];                     // W3 [k][oc] (tf32)
__device__ float g_wfcT[3136 * 512];                  // Wfc [k][n] (tf32)
__device__ float g_wihT[512 * 512];                   // W_ih [k][n] (tf32)

// ---------------------------------------------------------------------------
// cp.async helpers
// ---------------------------------------------------------------------------
__device__ __forceinline__ unsigned smem_u32(const void* p) {
    return (unsigned)__cvta_generic_to_shared(p);
}
#define CP16(dst, src) \
    asm volatile("cp.async.ca.shared.global [%0], [%1], 16;" \
                 :: "r"(smem_u32(dst)), "l"(src) : "memory")
#define CP_COMMIT() asm volatile("cp.async.commit_group;" ::: "memory")
#define CP_WAIT0()  asm volatile("cp.async.wait_group 0;" ::: "memory")
#define CP_WAIT1()  asm volatile("cp.async.wait_group 1;" ::: "memory")

// ---------------------------------------------------------------------------
// Weight re-layout preps (all tf32-rounded)
// ---------------------------------------------------------------------------
__global__ __launch_bounds__(256) void w1t_kernel(const float* __restrict__ W1) {
    const int id = blockIdx.x * 256 + threadIdx.x;
    const int k = id >> 5, oc = id & 31;
    g_w1t[k * 32 + oc] = wmma::__float_to_tf32(W1[oc * 64 + k] * (1.0f / 255.0f));
}
__global__ __launch_bounds__(256) void w2t_kernel(const float* __restrict__ W2) {
    const int id = blockIdx.x * 256 + threadIdx.x;
    const int k = id >> 6, oc = id & 63;
    const int c = k >> 7, k16 = (k & 127) >> 3, icl = k & 7;
    g_w2t[k * 64 + oc] = wmma::__float_to_tf32(W2[oc * 512 + (c * 8 + icl) * 16 + k16]);
}
__global__ __launch_bounds__(256) void w3t_kernel(const float* __restrict__ W3) {
    const int id = blockIdx.x * 256 + threadIdx.x;
    const int k = id >> 6, oc = id & 63;
    const int icc = k / 144, rem = k % 144, k9 = rem >> 4, icl = rem & 15;
    g_w3t[k * 64 + oc] = wmma::__float_to_tf32(W3[oc * 576 + (icc * 16 + icl) * 9 + k9]);
}
// Tiled transposes: both sides coalesced.
__global__ __launch_bounds__(256) void wfct_kernel(const float* __restrict__ Wfc) {
    __shared__ float t[32][33];
    const int k0 = blockIdx.x * 32, n0 = blockIdx.y * 32;
    const int tx = threadIdx.x & 31, ty = threadIdx.x >> 5;  // ty 0..7
#pragma unroll
    for (int i = ty; i < 32; i += 8)
        t[i][tx] = Wfc[(size_t)(n0 + i) * 3136 + k0 + tx];
    __syncthreads();
#pragma unroll
    for (int i = ty; i < 32; i += 8)
        g_wfcT[(size_t)(k0 + i) * 512 + n0 + tx] = wmma::__float_to_tf32(t[tx][i]);
}
__global__ __launch_bounds__(256) void wiht_kernel(const float* __restrict__ W_ih) {
    __shared__ float t[32][33];
    const int k0 = blockIdx.x * 32, n0 = blockIdx.y * 32;
    const int tx = threadIdx.x & 31, ty = threadIdx.x >> 5;
#pragma unroll
    for (int i = ty; i < 32; i += 8)
        t[i][tx] = W_ih[(size_t)(n0 + i) * 512 + k0 + tx];
    __syncthreads();
#pragma unroll
    for (int i = ty; i < 32; i += 8)
        g_wihT[(size_t)(k0 + i) * 512 + n0 + tx] = wmma::__float_to_tf32(t[tx][i]);
}
__global__ __launch_bounds__(512) void whh_transpose_kernel(const float* __restrict__ W_hh) {
    const int id = blockIdx.x * 512 + threadIdx.x;
    const int k = id >> 9, j = id & 511;
    g_whhT[k * 512 + j] = W_hh[j * 128 + k];
}

// ---------------------------------------------------------------------------
// Common WMMA defs
// ---------------------------------------------------------------------------
#define LDA 136     // conv1 col-major A
#define LDAR 20     // row-major A pad (mult of 4; 2-way bank repeat only)
#define LDB 72
#define LDC 72
#define LDB1 36
#define LDC1 36

typedef wmma::fragment<wmma::accumulator, 16, 16, 8, float> AccFrag;
typedef wmma::fragment<wmma::matrix_a, 16, 16, 8, wmma::precision::tf32, wmma::col_major> AFrag;
typedef wmma::fragment<wmma::matrix_a, 16, 16, 8, wmma::precision::tf32, wmma::row_major> AFragR;
typedef wmma::fragment<wmma::matrix_b, 16, 16, 8, wmma::precision::tf32, wmma::row_major> BFrag;

// converting copy (external input, conv1 only)
#define STAGE_A8C(dst, ar, kb, v0, v1)                                \
    {                                                                 \
        (dst)[((kb) + 0) * LDA + (ar)] = wmma::__float_to_tf32(v0.x); \
        (dst)[((kb) + 1) * LDA + (ar)] = wmma::__float_to_tf32(v0.y); \
        (dst)[((kb) + 2) * LDA + (ar)] = wmma::__float_to_tf32(v0.z); \
        (dst)[((kb) + 3) * LDA + (ar)] = wmma::__float_to_tf32(v0.w); \
        (dst)[((kb) + 4) * LDA + (ar)] = wmma::__float_to_tf32(v1.x); \
        (dst)[((kb) + 5) * LDA + (ar)] = wmma::__float_to_tf32(v1.y); \
        (dst)[((kb) + 6) * LDA + (ar)] = wmma::__float_to_tf32(v1.z); \
        (dst)[((kb) + 7) * LDA + (ar)] = wmma::__float_to_tf32(v1.w); \
    }

// row-major-A mma chunk (16 k): As[128][LDAR], Bs[16][LDB]
__device__ __forceinline__ void mma_chunkR(const float* __restrict__ As,
                                           const float* __restrict__ Bs,
                                           AccFrag (&acc)[2][2], int wm, int wn) {
#pragma unroll
    for (int ks = 0; ks < 16; ks += 8) {
        AFragR a[2]; BFrag b[2];
#pragma unroll
        for (int i = 0; i < 2; i++)
            wmma::load_matrix_sync(a[i], As + (wm * 32 + i * 16) * LDAR + ks, LDAR);
#pragma unroll
        for (int j = 0; j < 2; j++)
            wmma::load_matrix_sync(b[j], Bs + ks * LDB + wn * 32 + j * 16, LDB);
#pragma unroll
        for (int i = 0; i < 2; i++)
#pragma unroll
            for (int j = 0; j < 2; j++)
                wmma::mma_sync(acc[i][j], a[i], b[j], acc[i][j]);
    }
}

__device__ __forceinline__ void store_c_frags(float* smem, AccFrag (&acc)[2][2],
                                              int wm, int wn) {
#pragma unroll
    for (int i = 0; i < 2; i++)
#pragma unroll
        for (int j = 0; j < 2; j++)
            wmma::store_matrix_sync(&smem[(wm * 32 + i * 16) * LDC + wn * 32 + j * 16],
                                    acc[i][j], LDC, wmma::mem_row_major);
}

__device__ __forceinline__ float relu_t32(float v, float b) {
    return wmma::__float_to_tf32(fmaxf(v + b, 0.f));
}

// smem for 3-stage cp.async kernels (floats):
// As: 3 x 128*20 = 7680 @0 ; Bs: 3 x 16*72 = 3456 @7680 ; total 11136 (44.5KB)
// epilogue C [128][72]=9216 overlays from base.
#define ASR(sm, buf) ((sm) + (buf) * 2560)
#define BSR(sm, buf) ((sm) + 7680 + (buf) * 1152)
#define SMEM_FLOATS 11136

// ---------------------------------------------------------------------------
// conv1 TF32 WMMA (r11/r15 proven): M=1638400, N=32, K=64.
// ---------------------------------------------------------------------------
__global__ __launch_bounds__(256) void conv1_wmma_kernel(const float* __restrict__ x,
                                                         const float* __restrict__ b1) {
    __shared__ float smem[5504];
    const int tid = threadIdx.x;
    const int wid = tid >> 5, wm = wid >> 1, wn = wid & 1;
    const int m0 = blockIdx.x * 128;
    const int ar = tid >> 1, q = tid & 1;
    const int m = m0 + ar;
    const int an = m / 400, ap = m % 400;
    const int iy = (ap / 20) * 4, ix = (ap % 20) * 4;
    const float* xrow = x + (size_t)an * 7056 + ix;
    const int kb = tid >> 3, ob = (tid & 7) << 2;

    AccFrag acc1[2];
#pragma unroll
    for (int i = 0; i < 2; i++) wmma::fill_fragment(acc1[i], 0.f);

    float* As = smem;
    float* Bs = smem + 4352;

#define C1_LOADA(k0, v0, v1)                                   \
    {                                                          \
        const int ky = ((k0) >> 3) + q;                        \
        const float* xp = xrow + (iy + ky) * 84;               \
        v0 = *(const float4*)(xp);                             \
        v1 = *(const float4*)(xp + 4);                         \
    }

    {
        float4 a0, a1;
        C1_LOADA(0, a0, a1);
        float4 bv;
        if (tid < 128) bv = *(const float4*)&g_w1t[kb * 32 + ob];
        STAGE_A8C(As, ar, q * 8, a0, a1);
        if (tid < 128) *(float4*)&Bs[kb * LDB1 + ob] = bv;
    }
    __syncthreads();

    int buf = 0;
    for (int k0 = 16; k0 < 64; k0 += 16) {
        float4 a0, a1;
        C1_LOADA(k0, a0, a1);
        float4 bv;
        if (tid < 128) bv = *(const float4*)&g_w1t[(k0 + kb) * 32 + ob];
#pragma unroll
        for (int ks = 0; ks < 16; ks += 8) {
            AFrag a[2]; BFrag b;
#pragma unroll
            for (int i = 0; i < 2; i++)
                wmma::load_matrix_sync(a[i], As + buf * 2176 + ks * LDA + wm * 32 + i * 16, LDA);
            wmma::load_matrix_sync(b, Bs + buf * 576 + ks * LDB1 + wn * 16, LDB1);
#pragma unroll
            for (int i = 0; i < 2; i++)
                wmma::mma_sync(acc1[i], a[i], b, acc1[i]);
        }
        float* An = As + (buf ^ 1) * 2176;
        float* Bn = Bs + (buf ^ 1) * 576;
        STAGE_A8C(An, ar, q * 8, a0, a1);
        if (tid < 128) *(float4*)&Bn[kb * LDB1 + ob] = bv;
        __syncthreads();
        buf ^= 1;
    }
#pragma unroll
    for (int ks = 0; ks < 16; ks += 8) {
        AFrag a[2]; BFrag b;
#pragma unroll
        for (int i = 0; i < 2; i++)
            wmma::load_matrix_sync(a[i], As + buf * 2176 + ks * LDA + wm * 32 + i * 16, LDA);
        wmma::load_matrix_sync(b, Bs + buf * 576 + ks * LDB1 + wn * 16, LDB1);
#pragma unroll
        for (int i = 0; i < 2; i++)
            wmma::mma_sync(acc1[i], a[i], b, acc1[i]);
    }
    __syncthreads();
#pragma unroll
    for (int i = 0; i < 2; i++)
        wmma::store_matrix_sync(&smem[(wm * 32 + i * 16) * LDC1 + wn * 16], acc1[i],
                                LDC1, wmma::mem_row_major);
    __syncthreads();

    const int r = tid >> 1, h = tid & 1;
    const int rn = (m0 + r) / 400, rp = (m0 + r) % 400;
#pragma unroll
    for (int j = 0; j < 2; j++) {
        const int oc4 = h * 16 + j * 8;
#pragma unroll
        for (int s = 0; s < 2; s++) {
            const int oc = oc4 + s * 4;
            const float4 v = *(float4*)&smem[r * LDC1 + oc];
            const float4 bb = *(const float4*)&b1[oc];
            float4 o;
            o.x = relu_t32(v.x, bb.x);
            o.y = relu_t32(v.y, bb.y);
            o.z = relu_t32(v.z, bb.z);
            o.w = relu_t32(v.w, bb.w);
            const int g = oc >> 3, l = oc & 7;
            *(float4*)&g_z1[((size_t)rn * 4 + g) * 3200 + rp * 8 + l] = o;
        }
    }
}

// ---------------------------------------------------------------------------
// conv2 TF32 cp.async 3-stage: M=331776, K=512, N=64.
// ---------------------------------------------------------------------------
__global__ __launch_bounds__(256) void conv2_wmma_kernel(const float* __restrict__ b2) {
    __shared__ float smem[SMEM_FLOATS];
    const int tid = threadIdx.x;
    const int wid = tid >> 5, wm = wid >> 1, wn = wid & 1;
    const int m0 = blockIdx.x * 128;
    const int ar = tid >> 1, q = tid & 1;
    const int m = m0 + ar;
    const int an = m / 81, ap = m % 81;
    const int aiy = (ap / 9) * 2, aix = (ap % 9) * 2;
    const int kb = tid >> 4, ob = (tid & 15) << 2;

    AccFrag acc[2][2];
#pragma unroll
    for (int i = 0; i < 2; i++)
#pragma unroll
        for (int j = 0; j < 2; j++) wmma::fill_fragment(acc[i][j], 0.f);

#define C2_CPA(buf, k0)                                                          \
    {                                                                            \
        const int g = ((k0) >> 3) + q;                                           \
        const int c = g >> 4, k16 = g & 15;                                      \
        const int ky = k16 >> 2, kx = k16 & 3;                                   \
        const float* p = &g_z1[(((size_t)an * 4 + c) * 400 +                     \
                                (aiy + ky) * 20 + aix + kx) * 8];                \
        float* d = &ASR(smem, buf)[ar * LDAR + q * 8];                           \
        CP16(d, p); CP16(d + 4, p + 4);                                          \
        CP16(&BSR(smem, buf)[kb * LDB + ob], &g_w2t[(size_t)((k0) + kb) * 64 + ob]); \
    }

    C2_CPA(0, 0); CP_COMMIT();
    C2_CPA(1, 16); CP_COMMIT();

    int buf = 0;
    for (int k0 = 32; k0 < 512; k0 += 16) {
        CP_WAIT1();
        __syncthreads();
        const int nb = (buf + 2) % 3;
        C2_CPA(nb, k0); CP_COMMIT();
        mma_chunkR(ASR(smem, buf), BSR(smem, buf), acc, wm, wn);
        buf = (buf + 1) % 3;
    }
    CP_WAIT1(); __syncthreads();
    mma_chunkR(ASR(smem, buf), BSR(smem, buf), acc, wm, wn);
    buf = (buf + 1) % 3;
    CP_WAIT0(); __syncthreads();
    mma_chunkR(ASR(smem, buf), BSR(smem, buf), acc, wm, wn);
    __syncthreads();
    store_c_frags(smem, acc, wm, wn);
    __syncthreads();

    const int r = tid >> 1, h = tid & 1;
    const int rn = (m0 + r) / 81, rp = (m0 + r) % 81;
#pragma unroll
    for (int j = 0; j < 8; j++) {
        const int oc = h * 32 + j * 4;
        const float4 v = *(float4*)&smem[r * LDC + oc];
        const float4 bb = *(const float4*)&b2[oc];
        float4 o;
        o.x = relu_t32(v.x, bb.x);
        o.y = relu_t32(v.y, bb.y);
        o.z = relu_t32(v.z, bb.z);
        o.w = relu_t32(v.w, bb.w);
        *(float4*)&g_z2[(((size_t)rn * 4 + (oc >> 4)) * 81 + rp) * 16 + (oc & 15)] = o;
    }
}

// ---------------------------------------------------------------------------
// conv3 TF32 cp.async 3-stage: M=200704, K=576, N=64.
// ---------------------------------------------------------------------------
__global__ __launch_bounds__(256) void conv3_wmma_kernel(const float* __restrict__ b3) {
    __shared__ float smem[SMEM_FLOATS];
    const int tid = threadIdx.x;
    const int wid = tid >> 5, wm = wid >> 1, wn = wid & 1;
    const int m0 = blockIdx.x * 128;
    const int ar = tid >> 1, q = tid & 1;
    const int m = m0 + ar;
    const int an = m / 49, ap = m % 49;
    const int aoy = ap / 7, aox = ap % 7;
    const int kb = tid >> 4, ob = (tid & 15) << 2;

    AccFrag acc[2][2];
#pragma unroll
    for (int i = 0; i < 2; i++)
#pragma unroll
        for (int j = 0; j < 2; j++) wmma::fill_fragment(acc[i][j], 0.f);

#define C3_CPA(buf, k0)                                                          \
    {                                                                            \
        const int g = (k0) >> 4;                                                 \
        const int icc = g / 9, k9 = g % 9;                                       \
        const int ky = k9 / 3, kx = k9 % 3;                                      \
        const float* p = &g_z2[(((size_t)an * 4 + icc) * 81 +                    \
                                (aoy + ky) * 9 + aox + kx) * 16 + q * 8];        \
        float* d = &ASR(smem, buf)[ar * LDAR + q * 8];                           \
        CP16(d, p); CP16(d + 4, p + 4);                                          \
        CP16(&BSR(smem, buf)[kb * LDB + ob], &g_w3t[(size_t)((k0) + kb) * 64 + ob]); \
    }

    C3_CPA(0, 0); CP_COMMIT();
    C3_CPA(1, 16); CP_COMMIT();

    int buf = 0;
    for (int k0 = 32; k0 < 576; k0 += 16) {
        CP_WAIT1();
        __syncthreads();
        const int nb = (buf + 2) % 3;
        C3_CPA(nb, k0); CP_COMMIT();
        mma_chunkR(ASR(smem, buf), BSR(smem, buf), acc, wm, wn);
        buf = (buf + 1) % 3;
    }
    CP_WAIT1(); __syncthreads();
    mma_chunkR(ASR(smem, buf), BSR(smem, buf), acc, wm, wn);
    buf = (buf + 1) % 3;
    CP_WAIT0(); __syncthreads();
    mma_chunkR(ASR(smem, buf), BSR(smem, buf), acc, wm, wn);
    __syncthreads();
    store_c_frags(smem, acc, wm, wn);
    __syncthreads();

    const int r = tid >> 1, h = tid & 1;
    const int rn = (m0 + r) / 49, rp = (m0 + r) % 49;
#pragma unroll
    for (int j = 0; j < 8; j++) {
        const int oc = h * 32 + j * 4;
        const float4 v = *(float4*)&smem[r * LDC + oc];
        const float4 bb = *(const float4*)&b3[oc];
        float* zp = &g_z3[(size_t)rn * 3136 + oc * 49 + rp];
        zp[0]   = relu_t32(v.x, bb.x);
        zp[49]  = relu_t32(v.y, bb.y);
        zp[98]  = relu_t32(v.z, bb.z);
        zp[147] = relu_t32(v.w, bb.w);
    }
}

// ---------------------------------------------------------------------------
// Dense TF32 GEMM cp.async 3-stage (fc / gates): B from [k][n] weights.
// ---------------------------------------------------------------------------
__device__ __forceinline__ void gemm_wmma(const float* __restrict__ A,
                                          const float* __restrict__ Bt,  // [k][512]
                                          float* __restrict__ C, int K,
                                          const float* __restrict__ bias1,
                                          const float* __restrict__ bias2,
                                          bool relu, bool round_out) {
    __shared__ float smem[SMEM_FLOATS];
    const int tid = threadIdx.x;
    const int wid = tid >> 5, wm = wid >> 1, wn = wid & 1;
    const int m0 = blockIdx.y * 128, n0 = blockIdx.x * 64;
    const int ar = tid >> 1, q = tid & 1;
    const int kb = tid >> 4, ob = (tid & 15) << 2;
    const float* Ap = A + (size_t)(m0 + ar) * K + q * 8;
    const float* Btp = Bt + n0 + ob;

    AccFrag acc[2][2];
#pragma unroll
    for (int i = 0; i < 2; i++)
#pragma unroll
        for (int j = 0; j < 2; j++) wmma::fill_fragment(acc[i][j], 0.f);

#define G_CPA(buf, k0)                                                           \
    {                                                                            \
        const float* p = Ap + (k0);                                              \
        float* d = &ASR(smem, buf)[ar * LDAR + q * 8];                           \
        CP16(d, p); CP16(d + 4, p + 4);                                          \
        CP16(&BSR(smem, buf)[kb * LDB + ob], &Btp[(size_t)((k0) + kb) * 512]);   \
    }

    G_CPA(0, 0); CP_COMMIT();
    G_CPA(1, 16); CP_COMMIT();

    int buf = 0;
    for (int k0 = 32; k0 < K; k0 += 16) {
        CP_WAIT1();
        __syncthreads();
        const int nb = (buf + 2) % 3;
        G_CPA(nb, k0); CP_COMMIT();
        mma_chunkR(ASR(smem, buf), BSR(smem, buf), acc, wm, wn);
        buf = (buf + 1) % 3;
    }
    CP_WAIT1(); __syncthreads();
    mma_chunkR(ASR(smem, buf), BSR(smem, buf), acc, wm, wn);
    buf = (buf + 1) % 3;
    CP_WAIT0(); __syncthreads();
    mma_chunkR(ASR(smem, buf), BSR(smem, buf), acc, wm, wn);
    __syncthreads();
    store_c_frags(smem, acc, wm, wn);
    __syncthreads();

    const int r = tid >> 1, h = tid & 1;
#pragma unroll
    for (int j = 0; j < 8; j++) {
        const int c = h * 32 + j * 4;
        float4 v = *(float4*)&smem[r * LDC + c];
        const float b0 = bias1[n0 + c + 0] + (bias2 ? bias2[n0 + c + 0] : 0.f);
        const float b1v = bias1[n0 + c + 1] + (bias2 ? bias2[n0 + c + 1] : 0.f);
        const float b2v = bias1[n0 + c + 2] + (bias2 ? bias2[n0 + c + 2] : 0.f);
        const float b3v = bias1[n0 + c + 3] + (bias2 ? bias2[n0 + c + 3] : 0.f);
        v.x += b0; v.y += b1v; v.z += b2v; v.w += b3v;
        if (relu) {
            v.x = fmaxf(v.x, 0.f); v.y = fmaxf(v.y, 0.f);
            v.z = fmaxf(v.z, 0.f); v.w = fmaxf(v.w, 0.f);
        }
        if (round_out) {
            v.x = wmma::__float_to_tf32(v.x);
            v.y = wmma::__float_to_tf32(v.y);
            v.z = wmma::__float_to_tf32(v.z);
            v.w = wmma::__float_to_tf32(v.w);
        }
        *(float4*)&C[(size_t)(m0 + r) * 512 + n0 + c] = v;
    }
}

__global__ __launch_bounds__(256) void fc_gemm_kernel(const float* __restrict__ bfc) {
    gemm_wmma(g_z3, g_wfcT, g_hidden, 3136, bfc, nullptr, true, true);
}
__global__ __launch_bounds__(256) void gates_gemm_kernel(const float* __restrict__ b_ih,
                                                         const float* __restrict__ b_hh) {
    gemm_wmma(g_hidden, g_wihT, g_gates, 512, b_ih, b_hh, false, false);
}

// ---------------------------------------------------------------------------
// LSTM: one block per batch element, 512 threads (proven coalesced, fp32).
// ---------------------------------------------------------------------------
__device__ __forceinline__ float sigmoidf_(float v) {
    return 1.0f / (1.0f + __expf(-v));
}

__global__ __launch_bounds__(512) void lstm_kernel(const float* __restrict__ done,
                                                   const float* __restrict__ h0,
                                                   const float* __restrict__ c0,
                                                   float* __restrict__ out) {
    __shared__ float hm[HID];
    __shared__ float cs[HID];
    __shared__ float hs[HID];
    __shared__ float part[4 * 512];
    const int b = blockIdx.x;
    const int tid = threadIdx.x;
    const int j4 = tid & 127;
    const int ks = tid >> 7;

    if (tid < HID) {
        hs[tid] = h0[b * HID + tid];
        cs[tid] = c0[b * HID + tid];
    }
    __syncthreads();

    for (int t = 0; t < TSTEPS; t++) {
        const float mask = 1.0f - done[t * BATCH + b];
        if (tid < HID) hm[tid] = hs[tid] * mask;
        __syncthreads();

        float a0 = 0.f, a1 = 0.f, a2 = 0.f, a3 = 0.f;
        const float4* __restrict__ wt = (const float4*)&g_whhT[(ks * 32) * 512] + j4;
        const float* __restrict__ hk = &hm[ks * 32];
#pragma unroll
        for (int kk = 0; kk < 32; kk++) {
            const float4 w = wt[kk * 128];
            const float h = hk[kk];
            a0 += w.x * h; a1 += w.y * h; a2 += w.z * h; a3 += w.w * h;
        }
        float4 pv = {a0, a1, a2, a3};
        *(float4*)&part[ks * 512 + j4 * 4] = pv;
        __syncthreads();

        const float gx = g_gates[(size_t)(t * BATCH + b) * 512 + tid];
        const float gsum = part[tid] + part[512 + tid] + part[1024 + tid] +
                           part[1536 + tid] + gx;
        part[tid] = gsum;
        __syncthreads();

        if (tid < HID) {
            const float gi = part[tid];
            const float gf = part[tid + 128];
            const float gc = part[tid + 256];
            const float go = part[tid + 384];
            float c = cs[tid] * mask;
            c = sigmoidf_(gf) * c + sigmoidf_(gi) * tanhf(gc);
            const float h = sigmoidf_(go) * tanhf(c);
            cs[tid] = c;
            hs[tid] = h;
            g_hs[(size_t)(t * BATCH + b) * HID + tid] = h;
            if (t == TSTEPS - 1) {
                out[28672 + b * HID + tid] = h;
                out[32768 + b * HID + tid] = c;
            }
        }
        __syncthreads();
    }
}

// ---------------------------------------------------------------------------
// Heads: logits (4096x6) and value (4096x1) from g_hs.
// ---------------------------------------------------------------------------
__global__ __launch_bounds__(256) void heads_kernel(const float* __restrict__ Wa,
                                                    const float* __restrict__ ba,
                                                    const float* __restrict__ Wc,
                                                    const float* __restrict__ bc,
                                                    float* __restrict__ out) {
    __shared__ float was[6 * 128];
    __shared__ float wcs[128];
    __shared__ float bas[6];
    __shared__ float bcs;
    const int tid = threadIdx.x;
    for (int i = tid; i < 768; i += 256) was[i] = Wa[i];
    if (tid < 128) wcs[tid] = Wc[tid];
    if (tid < 6) bas[tid] = ba[tid];
    if (tid == 0) bcs = bc[0];
    __syncthreads();

    const int row = blockIdx.x * 256 + tid;
    const float* hp = &g_hs[(size_t)row * 128];
    float acc[6] = {0.f, 0.f, 0.f, 0.f, 0.f, 0.f};
    float accv = 0.f;
    for (int k = 0; k < 128; k += 4) {
        const float4 h4 = *(const float4*)&hp[k];
#pragma unroll
        for (int a = 0; a < 6; a++) {
            const float4 w4 = *(const float4*)&was[a * 128 + k];
            acc[a] += h4.x * w4.x + h4.y * w4.y + h4.z * w4.z + h4.w * w4.w;
        }
        const float4 wc4 = *(const float4*)&wcs[k];
        accv += h4.x * wc4.x + h4.y * wc4.y + h4.z * wc4.z + h4.w * wc4.w;
    }
#pragma unroll
    for (int a = 0; a < 6; a++) out[row * 6 + a] = acc[a] + bas[a];
    out[24576 + row] = accv + bcs;
}

// ---------------------------------------------------------------------------
// Launch
// ---------------------------------------------------------------------------
extern "C" void kernel_launch(void* const* d_in, const int* in_sizes, int n_in,
                              void* d_out, int out_size) {
    const float* x    = (const float*)d_in[0];
    const float* done = (const float*)d_in[1];
    const float* h0   = (const float*)d_in[2];
    const float* c0   = (const float*)d_in[3];
    const float* W1   = (const float*)d_in[4];
    const float* b1   = (const float*)d_in[5];
    const float* W2   = (const float*)d_in[6];
    const float* b2   = (const float*)d_in[7];
    const float* W3   = (const float*)d_in[8];
    const float* b3   = (const float*)d_in[9];
    const float* Wfc  = (const float*)d_in[10];
    const float* bfc  = (const float*)d_in[11];
    const float* W_ih = (const float*)d_in[12];
    const float* W_hh = (const float*)d_in[13];
    const float* b_ih = (const float*)d_in[14];
    const float* b_hh = (const float*)d_in[15];
    const float* Wa   = (const float*)d_in[16];
    const float* ba   = (const float*)d_in[17];
    const float* Wc   = (const float*)d_in[18];
    const float* bc   = (const float*)d_in[19];
    float* out = (float*)d_out;

    whh_transpose_kernel<<<128, 512>>>(W_hh);
    w1t_kernel<<<8, 256>>>(W1);
    w2t_kernel<<<128, 256>>>(W2);
    w3t_kernel<<<144, 256>>>(W3);
    wfct_kernel<<<dim3(98, 16), 256>>>(Wfc);
    wiht_kernel<<<dim3(16, 16), 256>>>(W_ih);
    conv1_wmma_kernel<<<12800, 256>>>(x, b1);
    conv2_wmma_kernel<<<2592, 256>>>(b2);
    conv3_wmma_kernel<<<1568, 256>>>(b3);
    fc_gemm_kernel<<<dim3(8, 32), 256>>>(bfc);
    gates_gemm_kernel<<<dim3(8, 32), 256>>>(b_ih, b_hh);
    lstm_kernel<<<BATCH, 512>>>(done, h0, c0, out);
    heads_kernel<<<16, 256>>>(Wa, ba, Wc, bc, out);
}

// round 17
// speedup vs baseline: 1.2280x; 1.0228x over previous
#include <cuda_runtime.h>
#include <mma.h>
#include <cstdint>

using namespace nvcuda;

#define NIMG   4096
#define TSTEPS 128
#define BATCH  32
#define HID    128

// Scratch (device globals; no allocation allowed)
__device__ float g_z1[(size_t)NIMG * 4 * 400 * 8];    // conv1 out (tf32-rounded)
__device__ float g_z2[(size_t)NIMG * 4 * 81 * 16];    // conv2 out (tf32-rounded)
__device__ float g_z3[(size_t)NIMG * 3136];           // conv3 out (tf32-rounded)
__device__ float g_hidden[(size_t)NIMG * 512];        // FC out (tf32-rounded)
__device__ float g_gates[(size_t)NIMG * 512];         // x-proj of gates (fp32)
__device__ float g_hs[(size_t)NIMG * HID];            // per-step hidden outputs
__device__ float g_whhT[HID * 512];                   // W_hh transposed
__device__ float g_w1t[64 * 32];                      // W1/255 [k][oc] (tf32)
__device__ float g_w2t[512 * 64];                     // W2 [k][oc] (tf32)
__device__ float g_w3t[576 * 64];                     // W3 [k][oc] (tf32)
__device__ float g_wfcT[3136 * 512];                  // Wfc [k][n] (tf32)
__device__ float g_wihT[512 * 512];                   // W_ih [k][n] (tf32)

// ---------------------------------------------------------------------------
// cp.async helpers
// ---------------------------------------------------------------------------
__device__ __forceinline__ unsigned smem_u32(const void* p) {
    return (unsigned)__cvta_generic_to_shared(p);
}
#define CP16(dst, src) \
    asm volatile("cp.async.ca.shared.global [%0], [%1], 16;" \
                 :: "r"(smem_u32(dst)), "l"(src) : "memory")
#define CP_COMMIT() asm volatile("cp.async.commit_group;" ::: "memory")
#define CP_WAIT0()  asm volatile("cp.async.wait_group 0;" ::: "memory")
#define CP_WAIT1()  asm volatile("cp.async.wait_group 1;" ::: "memory")

// ---------------------------------------------------------------------------
// Fused small preps (w1t / w2t / w3t / whhT) + tiled transposes for big ones
// ---------------------------------------------------------------------------
__global__ __launch_bounds__(256) void preps_kernel(const float* __restrict__ W1,
                                                    const float* __restrict__ W2,
                                                    const float* __restrict__ W3,
                                                    const float* __restrict__ W_hh) {
    int id = blockIdx.x * 256 + threadIdx.x;
    if (id < 2048) {
        const int k = id >> 5, oc = id & 31;
        g_w1t[k * 32 + oc] = wmma::__float_to_tf32(W1[oc * 64 + k] * (1.0f / 255.0f));
        return;
    }
    id -= 2048;
    if (id < 32768) {
        const int k = id >> 6, oc = id & 63;
        const int c = k >> 7, k16 = (k & 127) >> 3, icl = k & 7;
        g_w2t[k * 64 + oc] = wmma::__float_to_tf32(W2[oc * 512 + (c * 8 + icl) * 16 + k16]);
        return;
    }
    id -= 32768;
    if (id < 36864) {
        const int k = id >> 6, oc = id & 63;
        const int icc = k / 144, rem = k % 144, k9 = rem >> 4, icl = rem & 15;
        g_w3t[k * 64 + oc] = wmma::__float_to_tf32(W3[oc * 576 + (icc * 16 + icl) * 9 + k9]);
        return;
    }
    id -= 36864;
    if (id < 65536) {
        const int k = id >> 9, j = id & 511;
        g_whhT[k * 512 + j] = W_hh[j * 128 + k];
    }
}
__global__ __launch_bounds__(256) void wfct_kernel(const float* __restrict__ Wfc) {
    __shared__ float t[32][33];
    const int k0 = blockIdx.x * 32, n0 = blockIdx.y * 32;
    const int tx = threadIdx.x & 31, ty = threadIdx.x >> 5;
#pragma unroll
    for (int i = ty; i < 32; i += 8)
        t[i][tx] = Wfc[(size_t)(n0 + i) * 3136 + k0 + tx];
    __syncthreads();
#pragma unroll
    for (int i = ty; i < 32; i += 8)
        g_wfcT[(size_t)(k0 + i) * 512 + n0 + tx] = wmma::__float_to_tf32(t[tx][i]);
}
__global__ __launch_bounds__(256) void wiht_kernel(const float* __restrict__ W_ih) {
    __shared__ float t[32][33];
    const int k0 = blockIdx.x * 32, n0 = blockIdx.y * 32;
    const int tx = threadIdx.x & 31, ty = threadIdx.x >> 5;
#pragma unroll
    for (int i = ty; i < 32; i += 8)
        t[i][tx] = W_ih[(size_t)(n0 + i) * 512 + k0 + tx];
    __syncthreads();
#pragma unroll
    for (int i = ty; i < 32; i += 8)
        g_wihT[(size_t)(k0 + i) * 512 + n0 + tx] = wmma::__float_to_tf32(t[tx][i]);
}

// ---------------------------------------------------------------------------
// Common WMMA defs
// ---------------------------------------------------------------------------
#define LDAR 20     // row-major A pad
#define LDB 72
#define LDC 72
#define LDB1 36
#define LDC1 36

typedef wmma::fragment<wmma::accumulator, 16, 16, 8, float> AccFrag;
typedef wmma::fragment<wmma::matrix_a, 16, 16, 8, wmma::precision::tf32, wmma::row_major> AFragR;
typedef wmma::fragment<wmma::matrix_b, 16, 16, 8, wmma::precision::tf32, wmma::row_major> BFrag;

// row-major-A mma chunk (16 k): As[128][LDAR], Bs[16][LDB]
__device__ __forceinline__ void mma_chunkR(const float* __restrict__ As,
                                           const float* __restrict__ Bs,
                                           AccFrag (&acc)[2][2], int wm, int wn) {
#pragma unroll
    for (int ks = 0; ks < 16; ks += 8) {
        AFragR a[2]; BFrag b[2];
#pragma unroll
        for (int i = 0; i < 2; i++)
            wmma::load_matrix_sync(a[i], As + (wm * 32 + i * 16) * LDAR + ks, LDAR);
#pragma unroll
        for (int j = 0; j < 2; j++)
            wmma::load_matrix_sync(b[j], Bs + ks * LDB + wn * 32 + j * 16, LDB);
#pragma unroll
        for (int i = 0; i < 2; i++)
#pragma unroll
            for (int j = 0; j < 2; j++)
                wmma::mma_sync(acc[i][j], a[i], b[j], acc[i][j]);
    }
}

__device__ __forceinline__ void store_c_frags(float* smem, AccFrag (&acc)[2][2],
                                              int wm, int wn) {
#pragma unroll
    for (int i = 0; i < 2; i++)
#pragma unroll
        for (int j = 0; j < 2; j++)
            wmma::store_matrix_sync(&smem[(wm * 32 + i * 16) * LDC + wn * 32 + j * 16],
                                    acc[i][j], LDC, wmma::mem_row_major);
}

__device__ __forceinline__ float relu_t32(float v, float b) {
    return wmma::__float_to_tf32(fmaxf(v + b, 0.f));
}
__device__ __forceinline__ float4 cvt4(float4 v) {
    float4 r;
    r.x = wmma::__float_to_tf32(v.x);
    r.y = wmma::__float_to_tf32(v.y);
    r.z = wmma::__float_to_tf32(v.z);
    r.w = wmma::__float_to_tf32(v.w);
    return r;
}

// smem for 3-stage cp.async kernels (floats):
#define ASR(sm, buf) ((sm) + (buf) * 2560)
#define BSR(sm, buf) ((sm) + 7680 + (buf) * 1152)
#define SMEM_FLOATS 11136

// ---------------------------------------------------------------------------
// conv1 TF32 WMMA, row-major A + vector STS + cp.async B: M=1638400, N=32, K=64.
// ---------------------------------------------------------------------------
__global__ __launch_bounds__(256) void conv1_wmma_kernel(const float* __restrict__ x,
                                                         const float* __restrict__ b1) {
    __shared__ float smem[6272];   // As 2x2560 @0, Bs 2x576 @5120; C 128x36 overlays
    const int tid = threadIdx.x;
    const int wid = tid >> 5, wm = wid >> 1, wn = wid & 1;
    const int m0 = blockIdx.x * 128;
    const int ar = tid >> 1, q = tid & 1;
    const int m = m0 + ar;
    const int an = m / 400, ap = m % 400;
    const int iy = (ap / 20) * 4, ix = (ap % 20) * 4;
    const float* xrow = x + (size_t)an * 7056 + ix;
    const int kb = tid >> 3, ob = (tid & 7) << 2;   // B loader: tid<128

    AccFrag acc1[2];
#pragma unroll
    for (int i = 0; i < 2; i++) wmma::fill_fragment(acc1[i], 0.f);

    float* As = smem;
    float* Bs = smem + 5120;

#define C1_LOAD(k0, r0, r1)                                    \
    {                                                          \
        const int ky = ((k0) >> 3) + q;                        \
        const float* xp = xrow + (iy + ky) * 84;               \
        r0 = cvt4(*(const float4*)(xp));                       \
        r1 = cvt4(*(const float4*)(xp + 4));                   \
    }
#define C1_STORE(buf, r0, r1)                                  \
    {                                                          \
        float* d = &As[(buf) * 2560 + ar * LDAR + q * 8];      \
        *(float4*)d = r0; *(float4*)(d + 4) = r1;              \
    }
#define C1_B(buf, k0)                                          \
    if (tid < 128)                                             \
        CP16(&Bs[(buf) * 576 + kb * LDB1 + ob], &g_w1t[((k0) + kb) * 32 + ob]);

#define C1_MMA(buf)                                                              \
    {                                                                            \
        _Pragma("unroll")                                                        \
        for (int ks = 0; ks < 16; ks += 8) {                                     \
            AFragR a[2]; BFrag b;                                                \
            _Pragma("unroll")                                                    \
            for (int i = 0; i < 2; i++)                                          \
                wmma::load_matrix_sync(a[i],                                     \
                    As + (buf) * 2560 + (wm * 32 + i * 16) * LDAR + ks, LDAR);   \
            wmma::load_matrix_sync(b, Bs + (buf) * 576 + ks * LDB1 + wn * 16,    \
                                   LDB1);                                        \
            _Pragma("unroll")                                                    \
            for (int i = 0; i < 2; i++)                                          \
                wmma::mma_sync(acc1[i], a[i], b, acc1[i]);                       \
        }                                                                        \
    }

    {
        float4 r0, r1;
        C1_LOAD(0, r0, r1);
        C1_B(0, 0); CP_COMMIT();
        C1_STORE(0, r0, r1);
        CP_WAIT0();
    }
    __syncthreads();

    int buf = 0;
    for (int k0 = 16; k0 < 64; k0 += 16) {
        float4 r0, r1;
        C1_LOAD(k0, r0, r1);
        C1_B(buf ^ 1, k0); CP_COMMIT();
        C1_MMA(buf);
        C1_STORE(buf ^ 1, r0, r1);
        CP_WAIT0();
        __syncthreads();
        buf ^= 1;
    }
    C1_MMA(buf);
    __syncthreads();
#pragma unroll
    for (int i = 0; i < 2; i++)
        wmma::store_matrix_sync(&smem[(wm * 32 + i * 16) * LDC1 + wn * 16], acc1[i],
                                LDC1, wmma::mem_row_major);
    __syncthreads();

    const int r = tid >> 1, h = tid & 1;
    const int rn = (m0 + r) / 400, rp = (m0 + r) % 400;
#pragma unroll
    for (int j = 0; j < 2; j++) {
        const int oc4 = h * 16 + j * 8;
#pragma unroll
        for (int s = 0; s < 2; s++) {
            const int oc = oc4 + s * 4;
            const float4 v = *(float4*)&smem[r * LDC1 + oc];
            const float4 bb = *(const float4*)&b1[oc];
            float4 o;
            o.x = relu_t32(v.x, bb.x);
            o.y = relu_t32(v.y, bb.y);
            o.z = relu_t32(v.z, bb.z);
            o.w = relu_t32(v.w, bb.w);
            const int g = oc >> 3, l = oc & 7;
            *(float4*)&g_z1[((size_t)rn * 4 + g) * 3200 + rp * 8 + l] = o;
        }
    }
}

// ---------------------------------------------------------------------------
// conv2 TF32 cp.async 3-stage (r16 proven): M=331776, K=512, N=64.
// ---------------------------------------------------------------------------
__global__ __launch_bounds__(256) void conv2_wmma_kernel(const float* __restrict__ b2) {
    __shared__ float smem[SMEM_FLOATS];
    const int tid = threadIdx.x;
    const int wid = tid >> 5, wm = wid >> 1, wn = wid & 1;
    const int m0 = blockIdx.x * 128;
    const int ar = tid >> 1, q = tid & 1;
    const int m = m0 + ar;
    const int an = m / 81, ap = m % 81;
    const int aiy = (ap / 9) * 2, aix = (ap % 9) * 2;
    const int kb = tid >> 4, ob = (tid & 15) << 2;

    AccFrag acc[2][2];
#pragma unroll
    for (int i = 0; i < 2; i++)
#pragma unroll
        for (int j = 0; j < 2; j++) wmma::fill_fragment(acc[i][j], 0.f);

#define C2_CPA(buf, k0)                                                          \
    {                                                                            \
        const int g = ((k0) >> 3) + q;                                           \
        const int c = g >> 4, k16 = g & 15;                                      \
        const int ky = k16 >> 2, kx = k16 & 3;                                   \
        const float* p = &g_z1[(((size_t)an * 4 + c) * 400 +                     \
                                (aiy + ky) * 20 + aix + kx) * 8];                \
        float* d = &ASR(smem, buf)[ar * LDAR + q * 8];                           \
        CP16(d, p); CP16(d + 4, p + 4);                                          \
        CP16(&BSR(smem, buf)[kb * LDB + ob], &g_w2t[(size_t)((k0) + kb) * 64 + ob]); \
    }

    C2_CPA(0, 0); CP_COMMIT();
    C2_CPA(1, 16); CP_COMMIT();

    int buf = 0;
    for (int k0 = 32; k0 < 512; k0 += 16) {
        CP_WAIT1();
        __syncthreads();
        const int nb = (buf + 2) % 3;
        C2_CPA(nb, k0); CP_COMMIT();
        mma_chunkR(ASR(smem, buf), BSR(smem, buf), acc, wm, wn);
        buf = (buf + 1) % 3;
    }
    CP_WAIT1(); __syncthreads();
    mma_chunkR(ASR(smem, buf), BSR(smem, buf), acc, wm, wn);
    buf = (buf + 1) % 3;
    CP_WAIT0(); __syncthreads();
    mma_chunkR(ASR(smem, buf), BSR(smem, buf), acc, wm, wn);
    __syncthreads();
    store_c_frags(smem, acc, wm, wn);
    __syncthreads();

    const int r = tid >> 1, h = tid & 1;
    const int rn = (m0 + r) / 81, rp = (m0 + r) % 81;
#pragma unroll
    for (int j = 0; j < 8; j++) {
        const int oc = h * 32 + j * 4;
        const float4 v = *(float4*)&smem[r * LDC + oc];
        const float4 bb = *(const float4*)&b2[oc];
        float4 o;
        o.x = relu_t32(v.x, bb.x);
        o.y = relu_t32(v.y, bb.y);
        o.z = relu_t32(v.z, bb.z);
        o.w = relu_t32(v.w, bb.w);
        *(float4*)&g_z2[(((size_t)rn * 4 + (oc >> 4)) * 81 + rp) * 16 + (oc & 15)] = o;
    }
}

// ---------------------------------------------------------------------------
// conv3 TF32 cp.async 3-stage (r16 proven): M=200704, K=576, N=64.
// ---------------------------------------------------------------------------
__global__ __launch_bounds__(256) void conv3_wmma_kernel(const float* __restrict__ b3) {
    __shared__ float smem[SMEM_FLOATS];
    const int tid = threadIdx.x;
    const int wid = tid >> 5, wm = wid >> 1, wn = wid & 1;
    const int m0 = blockIdx.x * 128;
    const int ar = tid >> 1, q = tid & 1;
    const int m = m0 + ar;
    const int an = m / 49, ap = m % 49;
    const int aoy = ap / 7, aox = ap % 7;
    const int kb = tid >> 4, ob = (tid & 15) << 2;

    AccFrag acc[2][2];
#pragma unroll
    for (int i = 0; i < 2; i++)
#pragma unroll
        for (int j = 0; j < 2; j++) wmma::fill_fragment(acc[i][j], 0.f);

#define C3_CPA(buf, k0)                                                          \
    {                                                                            \
        const int g = (k0) >> 4;                                                 \
        const int icc = g / 9, k9 = g % 9;                                       \
        const int ky = k9 / 3, kx = k9 % 3;                                      \
        const float* p = &g_z2[(((size_t)an * 4 + icc) * 81 +                    \
                                (aoy + ky) * 9 + aox + kx) * 16 + q * 8];        \
        float* d = &ASR(smem, buf)[ar * LDAR + q * 8];                           \
        CP16(d, p); CP16(d + 4, p + 4);                                          \
        CP16(&BSR(smem, buf)[kb * LDB + ob], &g_w3t[(size_t)((k0) + kb) * 64 + ob]); \
    }

    C3_CPA(0, 0); CP_COMMIT();
    C3_CPA(1, 16); CP_COMMIT();

    int buf = 0;
    for (int k0 = 32; k0 < 576; k0 += 16) {
        CP_WAIT1();
        __syncthreads();
        const int nb = (buf + 2) % 3;
        C3_CPA(nb, k0); CP_COMMIT();
        mma_chunkR(ASR(smem, buf), BSR(smem, buf), acc, wm, wn);
        buf = (buf + 1) % 3;
    }
    CP_WAIT1(); __syncthreads();
    mma_chunkR(ASR(smem, buf), BSR(smem, buf), acc, wm, wn);
    buf = (buf + 1) % 3;
    CP_WAIT0(); __syncthreads();
    mma_chunkR(ASR(smem, buf), BSR(smem, buf), acc, wm, wn);
    __syncthreads();
    store_c_frags(smem, acc, wm, wn);
    __syncthreads();

    const int r = tid >> 1, h = tid & 1;
    const int rn = (m0 + r) / 49, rp = (m0 + r) % 49;
#pragma unroll
    for (int j = 0; j < 8; j++) {
        const int oc = h * 32 + j * 4;
        const float4 v = *(float4*)&smem[r * LDC + oc];
        const float4 bb = *(const float4*)&b3[oc];
        float* zp = &g_z3[(size_t)rn * 3136 + oc * 49 + rp];
        zp[0]   = relu_t32(v.x, bb.x);
        zp[49]  = relu_t32(v.y, bb.y);
        zp[98]  = relu_t32(v.z, bb.z);
        zp[147] = relu_t32(v.w, bb.w);
    }
}

// ---------------------------------------------------------------------------
// Dense TF32 GEMM cp.async 3-stage (r16 proven): fc / gates.
// ---------------------------------------------------------------------------
__device__ __forceinline__ void gemm_wmma(const float* __restrict__ A,
                                          const float* __restrict__ Bt,  // [k][512]
                                          float* __restrict__ C, int K,
                                          const float* __restrict__ bias1,
                                          const float* __restrict__ bias2,
                                          bool relu, bool round_out) {
    __shared__ float smem[SMEM_FLOATS];
    const int tid = threadIdx.x;
    const int wid = tid >> 5, wm = wid >> 1, wn = wid & 1;
    const int m0 = blockIdx.y * 128, n0 = blockIdx.x * 64;
    const int ar = tid >> 1, q = tid & 1;
    const int kb = tid >> 4, ob = (tid & 15) << 2;
    const float* Ap = A + (size_t)(m0 + ar) * K + q * 8;
    const float* Btp = Bt + n0 + ob;

    AccFrag acc[2][2];
#pragma unroll
    for (int i = 0; i < 2; i++)
#pragma unroll
        for (int j = 0; j < 2; j++) wmma::fill_fragment(acc[i][j], 0.f);

#define G_CPA(buf, k0)                                                           \
    {                                                                            \
        const float* p = Ap + (k0);                                              \
        float* d = &ASR(smem, buf)[ar * LDAR + q * 8];                           \
        CP16(d, p); CP16(d + 4, p + 4);                                          \
        CP16(&BSR(smem, buf)[kb * LDB + ob], &Btp[(size_t)((k0) + kb) * 512]);   \
    }

    G_CPA(0, 0); CP_COMMIT();
    G_CPA(1, 16); CP_COMMIT();

    int buf = 0;
    for (int k0 = 32; k0 < K; k0 += 16) {
        CP_WAIT1();
        __syncthreads();
        const int nb = (buf + 2) % 3;
        G_CPA(nb, k0); CP_COMMIT();
        mma_chunkR(ASR(smem, buf), BSR(smem, buf), acc, wm, wn);
        buf = (buf + 1) % 3;
    }
    CP_WAIT1(); __syncthreads();
    mma_chunkR(ASR(smem, buf), BSR(smem, buf), acc, wm, wn);
    buf = (buf + 1) % 3;
    CP_WAIT0(); __syncthreads();
    mma_chunkR(ASR(smem, buf), BSR(smem, buf), acc, wm, wn);
    __syncthreads();
    store_c_frags(smem, acc, wm, wn);
    __syncthreads();

    const int r = tid >> 1, h = tid & 1;
#pragma unroll
    for (int j = 0; j < 8; j++) {
        const int c = h * 32 + j * 4;
        float4 v = *(float4*)&smem[r * LDC + c];
        const float b0 = bias1[n0 + c + 0] + (bias2 ? bias2[n0 + c + 0] : 0.f);
        const float b1v = bias1[n0 + c + 1] + (bias2 ? bias2[n0 + c + 1] : 0.f);
        const float b2v = bias1[n0 + c + 2] + (bias2 ? bias2[n0 + c + 2] : 0.f);
        const float b3v = bias1[n0 + c + 3] + (bias2 ? bias2[n0 + c + 3] : 0.f);
        v.x += b0; v.y += b1v; v.z += b2v; v.w += b3v;
        if (relu) {
            v.x = fmaxf(v.x, 0.f); v.y = fmaxf(v.y, 0.f);
            v.z = fmaxf(v.z, 0.f); v.w = fmaxf(v.w, 0.f);
        }
        if (round_out) {
            v.x = wmma::__float_to_tf32(v.x);
            v.y = wmma::__float_to_tf32(v.y);
            v.z = wmma::__float_to_tf32(v.z);
            v.w = wmma::__float_to_tf32(v.w);
        }
        *(float4*)&C[(size_t)(m0 + r) * 512 + n0 + c] = v;
    }
}

__global__ __launch_bounds__(256) void fc_gemm_kernel(const float* __restrict__ bfc) {
    gemm_wmma(g_z3, g_wfcT, g_hidden, 3136, bfc, nullptr, true, true);
}
__global__ __launch_bounds__(256) void gates_gemm_kernel(const float* __restrict__ b_ih,
                                                         const float* __restrict__ b_hh) {
    gemm_wmma(g_hidden, g_wihT, g_gates, 512, b_ih, b_hh, false, false);
}

// ---------------------------------------------------------------------------
// LSTM: one block per batch element, 512 threads (proven coalesced, fp32).
// ---------------------------------------------------------------------------
__device__ __forceinline__ float sigmoidf_(float v) {
    return 1.0f / (1.0f + __expf(-v));
}

__global__ __launch_bounds__(512) void lstm_kernel(const float* __restrict__ done,
                                                   const float* __restrict__ h0,
                                                   const float* __restrict__ c0,
                                                   float* __restrict__ out) {
    __shared__ float hm[HID];
    __shared__ float cs[HID];
    __shared__ float hs[HID];
    __shared__ float part[4 * 512];
    const int b = blockIdx.x;
    const int tid = threadIdx.x;
    const int j4 = tid & 127;
    const int ks = tid >> 7;

    if (tid < HID) {
        hs[tid] = h0[b * HID + tid];
        cs[tid] = c0[b * HID + tid];
    }
    __syncthreads();

    for (int t = 0; t < TSTEPS; t++) {
        const float mask = 1.0f - done[t * BATCH + b];
        if (tid < HID) hm[tid] = hs[tid] * mask;
        __syncthreads();

        float a0 = 0.f, a1 = 0.f, a2 = 0.f, a3 = 0.f;
        const float4* __restrict__ wt = (const float4*)&g_whhT[(ks * 32) * 512] + j4;
        const float* __restrict__ hk = &hm[ks * 32];
#pragma unroll
        for (int kk = 0; kk < 32; kk++) {
            const float4 w = wt[kk * 128];
            const float h = hk[kk];
            a0 += w.x * h; a1 += w.y * h; a2 += w.z * h; a3 += w.w * h;
        }
        float4 pv = {a0, a1, a2, a3};
        *(float4*)&part[ks * 512 + j4 * 4] = pv;
        __syncthreads();

        const float gx = g_gates[(size_t)(t * BATCH + b) * 512 + tid];
        const float gsum = part[tid] + part[512 + tid] + part[1024 + tid] +
                           part[1536 + tid] + gx;
        part[tid] = gsum;
        __syncthreads();

        if (tid < HID) {
            const float gi = part[tid];
            const float gf = part[tid + 128];
            const float gc = part[tid + 256];
            const float go = part[tid + 384];
            float c = cs[tid] * mask;
            c = sigmoidf_(gf) * c + sigmoidf_(gi) * tanhf(gc);
            const float h = sigmoidf_(go) * tanhf(c);
            cs[tid] = c;
            hs[tid] = h;
            g_hs[(size_t)(t * BATCH + b) * HID + tid] = h;
            if (t == TSTEPS - 1) {
                out[28672 + b * HID + tid] = h;
                out[32768 + b * HID + tid] = c;
            }
        }
        __syncthreads();
    }
}

// ---------------------------------------------------------------------------
// Heads: logits (4096x6) and value (4096x1) from g_hs.
// ---------------------------------------------------------------------------
__global__ __launch_bounds__(256) void heads_kernel(const float* __restrict__ Wa,
                                                    const float* __restrict__ ba,
                                                    const float* __restrict__ Wc,
                                                    const float* __restrict__ bc,
                                                    float* __restrict__ out) {
    __shared__ float was[6 * 128];
    __shared__ float wcs[128];
    __shared__ float bas[6];
    __shared__ float bcs;
    const int tid = threadIdx.x;
    for (int i = tid; i < 768; i += 256) was[i] = Wa[i];
    if (tid < 128) wcs[tid] = Wc[tid];
    if (tid < 6) bas[tid] = ba[tid];
    if (tid == 0) bcs = bc[0];
    __syncthreads();

    const int row = blockIdx.x * 256 + tid;
    const float* hp = &g_hs[(size_t)row * 128];
    float acc[6] = {0.f, 0.f, 0.f, 0.f, 0.f, 0.f};
    float accv = 0.f;
    for (int k = 0; k < 128; k += 4) {
        const float4 h4 = *(const float4*)&hp[k];
#pragma unroll
        for (int a = 0; a < 6; a++) {
            const float4 w4 = *(const float4*)&was[a * 128 + k];
            acc[a] += h4.x * w4.x + h4.y * w4.y + h4.z * w4.z + h4.w * w4.w;
        }
        const float4 wc4 = *(const float4*)&wcs[k];
        accv += h4.x * wc4.x + h4.y * wc4.y + h4.z * wc4.z + h4.w * wc4.w;
    }
#pragma unroll
    for (int a = 0; a < 6; a++) out[row * 6 + a] = acc[a] + bas[a];
    out[24576 + row] = accv + bcs;
}

// ---------------------------------------------------------------------------
// Launch
// ---------------------------------------------------------------------------
extern "C" void kernel_launch(void* const* d_in, const int* in_sizes, int n_in,
                              void* d_out, int out_size) {
    const float* x    = (const float*)d_in[0];
    const float* done = (const float*)d_in[1];
    const float* h0   = (const float*)d_in[2];
    const float* c0   = (const float*)d_in[3];
    const float* W1   = (const float*)d_in[4];
    const float* b1   = (const float*)d_in[5];
    const float* W2   = (const float*)d_in[6];
    const float* b2   = (const float*)d_in[7];
    const float* W3   = (const float*)d_in[8];
    const float* b3   = (const float*)d_in[9];
    const float* Wfc  = (const float*)d_in[10];
    const float* bfc  = (const float*)d_in[11];
    const float* W_ih = (const float*)d_in[12];
    const float* W_hh = (const float*)d_in[13];
    const float* b_ih = (const float*)d_in[14];
    const float* b_hh = (const float*)d_in[15];
    const float* Wa   = (const float*)d_in[16];
    const float* ba   = (const float*)d_in[17];
    const float* Wc   = (const float*)d_in[18];
    const float* bc   = (const float*)d_in[19];
    float* out = (float*)d_out;

    preps_kernel<<<536, 256>>>(W1, W2, W3, W_hh);
    wfct_kernel<<<dim3(98, 16), 256>>>(Wfc);
    wiht_kernel<<<dim3(16, 16), 256>>>(W_ih);
    conv1_wmma_kernel<<<12800, 256>>>(x, b1);
    conv2_wmma_kernel<<<2592, 256>>>(b2);
    conv3_wmma_kernel<<<1568, 256>>>(b3);
    fc_gemm_kernel<<<dim3(8, 32), 256>>>(bfc);
    gates_gemm_kernel<<<dim3(8, 32), 256>>>(b_ih, b_hh);
    lstm_kernel<<<BATCH, 512>>>(done, h0, c0, out);
    heads_kernel<<<16, 256>>>(Wa, ba, Wc, bc, out);
}